// round 1
// baseline (speedup 1.0000x reference)
#include <cuda_runtime.h>

#define EMBED 768
#define HEADS 12
#define DKK   64
#define RDIM  128
#define CDIM  256
#define NTOK  (RDIM * CDIM)   // 32768

// Scratch (allocation-free rule: __device__ globals). g_q is reused as the
// attention context buffer (per-(c,h) slices are read before written within a
// single block; disjoint across blocks).
__device__ float g_q[(size_t)NTOK * EMBED];
__device__ float g_k[(size_t)NTOK * EMBED];
__device__ float g_v[(size_t)NTOK * EMBED];

// ---------------------------------------------------------------------------
// Tiled fp32 GEMM: Y[n, m] = (sum_k A[n,k] * W[m,k] + bias[m]) * scale
// A: [N, 768] row-major; W: [768, 768] row-major (torch [out,in]);
// block tile 64x64, K-tile 16, 256 threads, 4x4 per thread.
// ---------------------------------------------------------------------------
__global__ __launch_bounds__(256) void gemm_bias_kernel(
    const float* __restrict__ A, const float* __restrict__ W,
    const float* __restrict__ bias, float* __restrict__ Y, float scale)
{
    __shared__ float As[16 * 68];
    __shared__ float Bs[16 * 68];

    const int t  = threadIdx.x;
    const int tx = t & 15;
    const int ty = t >> 4;
    const int n0 = blockIdx.x * 64;
    const int m0 = blockIdx.y * 64;

    const int lrow = t >> 2;      // 0..63
    const int lf4  = t & 3;       // 0..3 (which float4 of the 16-wide K tile)
    const float* Aptr = A + (size_t)(n0 + lrow) * EMBED + lf4 * 4;
    const float* Wptr = W + (size_t)(m0 + lrow) * EMBED + lf4 * 4;

    float acc[4][4];
    #pragma unroll
    for (int i = 0; i < 4; i++)
        #pragma unroll
        for (int j = 0; j < 4; j++) acc[i][j] = 0.f;

    for (int k0 = 0; k0 < EMBED; k0 += 16) {
        float4 av = *(const float4*)(Aptr + k0);
        float4 bv = *(const float4*)(Wptr + k0);
        As[(lf4 * 4 + 0) * 68 + lrow] = av.x;
        As[(lf4 * 4 + 1) * 68 + lrow] = av.y;
        As[(lf4 * 4 + 2) * 68 + lrow] = av.z;
        As[(lf4 * 4 + 3) * 68 + lrow] = av.w;
        Bs[(lf4 * 4 + 0) * 68 + lrow] = bv.x;
        Bs[(lf4 * 4 + 1) * 68 + lrow] = bv.y;
        Bs[(lf4 * 4 + 2) * 68 + lrow] = bv.z;
        Bs[(lf4 * 4 + 3) * 68 + lrow] = bv.w;
        __syncthreads();

        #pragma unroll
        for (int kk = 0; kk < 16; kk++) {
            float4 a4 = *(const float4*)(As + kk * 68 + ty * 4);
            float4 b4 = *(const float4*)(Bs + kk * 68 + tx * 4);
            float ar[4] = {a4.x, a4.y, a4.z, a4.w};
            float br[4] = {b4.x, b4.y, b4.z, b4.w};
            #pragma unroll
            for (int i = 0; i < 4; i++)
                #pragma unroll
                for (int j = 0; j < 4; j++)
                    acc[i][j] += ar[i] * br[j];
        }
        __syncthreads();
    }

    const int m = m0 + tx * 4;
    float b0 = bias[m + 0], b1 = bias[m + 1], b2 = bias[m + 2], b3 = bias[m + 3];
    #pragma unroll
    for (int i = 0; i < 4; i++) {
        float4 r;
        r.x = (acc[i][0] + b0) * scale;
        r.y = (acc[i][1] + b1) * scale;
        r.z = (acc[i][2] + b2) * scale;
        r.w = (acc[i][3] + b3) * scale;
        *(float4*)(Y + (size_t)(n0 + ty * 4 + i) * EMBED + m) = r;
    }
}

// ---------------------------------------------------------------------------
// Attention kernel: one block per (col c, head h).
// Loads Q/K/V [128 x 64] tiles, computes S = Q·K^T (q pre-scaled), applies
// padding mask, softmax over j, writes probs, computes C = P·V, writes C into
// the (c, h) slice of the context buffer.
// Dynamic smem layout:
//   qT [64][129], kT [64][129]  (transposed, pad 129 -> conflict-free)
//   vS [128][68]                (row-major, pad 68, float4-aligned)
//   S  [128][129]
//   mk [128] bytes
// ---------------------------------------------------------------------------
__global__ __launch_bounds__(256) void attn_kernel(
    const float* __restrict__ gq, const float* __restrict__ gk,
    const float* __restrict__ gv, const unsigned char* __restrict__ mask,
    float* __restrict__ probs, float* __restrict__ cout, int write_probs)
{
    extern __shared__ float sm[];
    float* qT = sm;                        // 64*129
    float* kT = qT + 64 * 129;             // 64*129
    float* vS = kT + 64 * 129;             // 128*68
    float* S  = vS + 128 * 68;             // 128*129
    unsigned char* mk = (unsigned char*)(S + 128 * 129);

    const int c = blockIdx.x;
    const int h = blockIdx.y;
    const int t = threadIdx.x;
    const int tx = t & 15;
    const int ty = t >> 4;

    const size_t base = (size_t)c * EMBED + h * DKK;

    // Load tiles (coalesced over d)
    for (int idx = t; idx < RDIM * DKK; idx += 256) {
        int i = idx >> 6;
        int d = idx & 63;
        size_t g = (size_t)i * (CDIM * EMBED) + base + d;
        qT[d * 129 + i] = gq[g];
        kT[d * 129 + i] = gk[g];
        vS[i * 68 + d]  = gv[g];
    }
    if (t < RDIM) mk[t] = mask[(size_t)t * CDIM + c];
    __syncthreads();

    // ---- Scores: S[i][j] = sum_d q[i][d]*k[j][d] (8x8 per thread) ----
    {
        const int i0 = ty * 8;
        const int j0 = tx * 8;
        float acc[8][8];
        #pragma unroll
        for (int i = 0; i < 8; i++)
            #pragma unroll
            for (int j = 0; j < 8; j++) acc[i][j] = 0.f;

        for (int d = 0; d < DKK; d++) {
            float qr[8], kr[8];
            #pragma unroll
            for (int u = 0; u < 8; u++) qr[u] = qT[d * 129 + i0 + u];
            #pragma unroll
            for (int u = 0; u < 8; u++) kr[u] = kT[d * 129 + j0 + u];
            #pragma unroll
            for (int i = 0; i < 8; i++)
                #pragma unroll
                for (int j = 0; j < 8; j++)
                    acc[i][j] += qr[i] * kr[j];
        }
        #pragma unroll
        for (int i = 0; i < 8; i++)
            #pragma unroll
            for (int j = 0; j < 8; j++)
                S[(i0 + i) * 129 + (j0 + j)] = acc[i][j];
    }
    __syncthreads();

    // ---- Softmax over j (one warp handles 16 rows) ----
    {
        const int warp = t >> 5;
        const int lane = t & 31;
        for (int r = 0; r < 16; r++) {
            int i = warp * 16 + r;
            float vals[4];
            float mx = -1e30f;
            #pragma unroll
            for (int u = 0; u < 4; u++) {
                int j = lane + 32 * u;
                float s = S[i * 129 + j];
                if (mk[j]) s = -10000.f;
                vals[u] = s;
                mx = fmaxf(mx, s);
            }
            #pragma unroll
            for (int o = 16; o > 0; o >>= 1)
                mx = fmaxf(mx, __shfl_xor_sync(0xffffffffu, mx, o));
            float sum = 0.f;
            #pragma unroll
            for (int u = 0; u < 4; u++) {
                vals[u] = __expf(vals[u] - mx);
                sum += vals[u];
            }
            #pragma unroll
            for (int o = 16; o > 0; o >>= 1)
                sum += __shfl_xor_sync(0xffffffffu, sum, o);
            float inv = 1.f / sum;
            size_t pb = ((size_t)(h * CDIM + c) * RDIM + i) * RDIM;
            #pragma unroll
            for (int u = 0; u < 4; u++) {
                int j = lane + 32 * u;
                float p = vals[u] * inv;
                S[i * 129 + j] = p;
                if (write_probs) probs[pb + j] = p;
            }
        }
    }
    __syncthreads();

    // ---- PV: C[i][d] = sum_j P[i][j] * v[j][d] (8x4 per thread) ----
    {
        const int i0 = ty * 8;
        const int d0 = tx * 4;
        float acc[8][4];
        #pragma unroll
        for (int i = 0; i < 8; i++)
            #pragma unroll
            for (int d = 0; d < 4; d++) acc[i][d] = 0.f;

        for (int j = 0; j < RDIM; j++) {
            float4 vv = *(const float4*)(vS + j * 68 + d0);
            float vr[4] = {vv.x, vv.y, vv.z, vv.w};
            #pragma unroll
            for (int i = 0; i < 8; i++) {
                float p = S[(i0 + i) * 129 + j];
                #pragma unroll
                for (int d = 0; d < 4; d++)
                    acc[i][d] += p * vr[d];
            }
        }
        #pragma unroll
        for (int i = 0; i < 8; i++) {
            float4 r = make_float4(acc[i][0], acc[i][1], acc[i][2], acc[i][3]);
            *(float4*)(cout + (size_t)(i0 + i) * (CDIM * EMBED) + base + d0) = r;
        }
    }
}

// ---------------------------------------------------------------------------
extern "C" void kernel_launch(void* const* d_in, const int* in_sizes, int n_in,
                              void* d_out, int out_size)
{
    const float* x  = (const float*)d_in[0];
    const unsigned char* mask = (const unsigned char*)d_in[1];
    const float* Wq = (const float*)d_in[2];
    const float* bq = (const float*)d_in[3];
    const float* Wk = (const float*)d_in[4];
    const float* bk = (const float*)d_in[5];
    const float* Wv = (const float*)d_in[6];
    const float* bv = (const float*)d_in[7];
    const float* Wo = (const float*)d_in[8];
    const float* bo = (const float*)d_in[9];
    float* out = (float*)d_out;

    float *q, *k, *v;
    cudaGetSymbolAddress((void**)&q, g_q);
    cudaGetSymbolAddress((void**)&k, g_k);
    cudaGetSymbolAddress((void**)&v, g_v);

    const long long out_elems = (long long)NTOK * EMBED;             // 25,165,824
    const long long probs_elems = (long long)HEADS * CDIM * RDIM * RDIM; // 50,331,648
    int write_probs = ((long long)out_size >= out_elems + probs_elems) ? 1 : 0;
    float* probs = write_probs ? (out + out_elems) : nullptr;

    const int attn_smem = (64 * 129 * 2 + 128 * 68 + 128 * 129) * 4 + 128;
    cudaFuncSetAttribute(attn_kernel, cudaFuncAttributeMaxDynamicSharedMemorySize,
                         attn_smem);

    dim3 ggrid(NTOK / 64, EMBED / 64);   // (512, 12)
    const float scaling = 0.125f;        // DK^-0.5 = 1/8

    gemm_bias_kernel<<<ggrid, 256>>>(x, Wq, bq, q, scaling);
    gemm_bias_kernel<<<ggrid, 256>>>(x, Wk, bk, k, 1.f);
    gemm_bias_kernel<<<ggrid, 256>>>(x, Wv, bv, v, 1.f);

    dim3 agrid(CDIM, HEADS);             // (256, 12)
    attn_kernel<<<agrid, 256, attn_smem>>>(q, k, v, mask, probs, q, write_probs);

    gemm_bias_kernel<<<ggrid, 256>>>(q, Wo, bo, out, 1.f);
}

// round 3
// speedup vs baseline: 1.7403x; 1.7403x over previous
#include <cuda_runtime.h>
#include <cuda_bf16.h>
#include <cstdint>

#define EMBED 768
#define HEADS 12
#define DKK   64
#define RDIM  128
#define CDIM  256
#define NTOK  (RDIM * CDIM)   // 32768

// ---------------------------------------------------------------------------
// Scratch (allocation-free rule: __device__ globals).
// ---------------------------------------------------------------------------
__device__ float g_q[(size_t)NTOK * EMBED];
__device__ float g_k[(size_t)NTOK * EMBED];
__device__ float g_v[(size_t)NTOK * EMBED];
__device__ __nv_bfloat16 g_ahi[(size_t)NTOK * EMBED];
__device__ __nv_bfloat16 g_alo[(size_t)NTOK * EMBED];
__device__ __nv_bfloat16 g_whi[4 * (size_t)EMBED * EMBED];
__device__ __nv_bfloat16 g_wlo[4 * (size_t)EMBED * EMBED];

__device__ __forceinline__ uint32_t smem_u32(const void* p) {
    uint32_t a;
    asm("{ .reg .u64 t; cvta.to.shared.u64 t, %1; cvt.u32.u64 %0, t; }"
        : "=r"(a) : "l"(p));
    return a;
}

__device__ __forceinline__ void ldsm4(uint32_t (&r)[4], uint32_t addr) {
    asm volatile("ldmatrix.sync.aligned.m8n8.x4.shared.b16 {%0,%1,%2,%3}, [%4];"
                 : "=r"(r[0]), "=r"(r[1]), "=r"(r[2]), "=r"(r[3]) : "r"(addr));
}

__device__ __forceinline__ void mma16816(float (&c)[4], const uint32_t (&a)[4],
                                         uint32_t b0, uint32_t b1) {
    asm volatile(
        "mma.sync.aligned.m16n8k16.row.col.f32.bf16.bf16.f32 "
        "{%0,%1,%2,%3}, {%4,%5,%6,%7}, {%8,%9}, {%0,%1,%2,%3};"
        : "+f"(c[0]), "+f"(c[1]), "+f"(c[2]), "+f"(c[3])
        : "r"(a[0]), "r"(a[1]), "r"(a[2]), "r"(a[3]), "r"(b0), "r"(b1));
}

// ---------------------------------------------------------------------------
// split fp32 -> (hi bf16, lo bf16), vectorized by 4
// ---------------------------------------------------------------------------
__global__ __launch_bounds__(256) void split_kernel(
    const float4* __restrict__ src, __nv_bfloat16* __restrict__ hi,
    __nv_bfloat16* __restrict__ lo, int n4)
{
    int i = blockIdx.x * blockDim.x + threadIdx.x;
    if (i >= n4) return;
    float4 v = src[i];
    __nv_bfloat16 h0 = __float2bfloat16(v.x);
    __nv_bfloat16 h1 = __float2bfloat16(v.y);
    __nv_bfloat16 h2 = __float2bfloat16(v.z);
    __nv_bfloat16 h3 = __float2bfloat16(v.w);
    __nv_bfloat16 l0 = __float2bfloat16(v.x - __bfloat162float(h0));
    __nv_bfloat16 l1 = __float2bfloat16(v.y - __bfloat162float(h1));
    __nv_bfloat16 l2 = __float2bfloat16(v.z - __bfloat162float(h2));
    __nv_bfloat16 l3 = __float2bfloat16(v.w - __bfloat162float(h3));
    __nv_bfloat162* hp = (__nv_bfloat162*)(hi + (size_t)i * 4);
    __nv_bfloat162* lp = (__nv_bfloat162*)(lo + (size_t)i * 4);
    hp[0] = __nv_bfloat162(h0, h1);
    hp[1] = __nv_bfloat162(h2, h3);
    lp[0] = __nv_bfloat162(l0, l1);
    lp[1] = __nv_bfloat162(l2, l3);
}

// ---------------------------------------------------------------------------
// mma.sync split-bf16 GEMM: Y[n,m] = (sum_k A[n,k]*W[m,k] + bias[m]) * scale
// CTA 128x128, 8 warps (warp tile 64x32), K-chunk 32, double-buffered smem.
// 3 MMA passes per k-step: Ahi*Bhi + Ahi*Blo + Alo*Bhi.
// smem tile row = 32 bf16 data + 8 pad = 80 B (conflict-free ldmatrix).
// ---------------------------------------------------------------------------
#define KC      32
#define NCH     (EMBED / KC)          // 24
#define ROWB    80                    // bytes per padded smem row
#define TILEB   (128 * ROWB)          // 10240 B
#define STAGEB  (4 * TILEB)           // Ahi, Alo, Bhi, Blo

__global__ __launch_bounds__(256, 1) void mma_gemm(
    const __nv_bfloat16* __restrict__ Ahi, const __nv_bfloat16* __restrict__ Alo,
    const __nv_bfloat16* __restrict__ Bhi, const __nv_bfloat16* __restrict__ Blo,
    const float* __restrict__ bias, float* __restrict__ Y, float scale)
{
    extern __shared__ char smem[];
    const uint32_t sbase = smem_u32(smem);

    const int tid  = threadIdx.x;
    const int wid  = tid >> 5;
    const int lane = tid & 31;
    const int wm   = wid >> 2;            // 0..1 : 64-row slice
    const int wn   = wid & 3;             // 0..3 : 32-col slice
    const int row0 = blockIdx.x * 128;
    const int col0 = blockIdx.y * 128;

    float acc[4][4][4];
    #pragma unroll
    for (int mt = 0; mt < 4; mt++)
        #pragma unroll
        for (int nt = 0; nt < 4; nt++)
            #pragma unroll
            for (int u = 0; u < 4; u++) acc[mt][nt][u] = 0.f;

    // ldmatrix source addresses (within a tile), depend only on lane:
    // A x4: row = (lane & 15), col8 = (lane >> 4)       [16x16 m-tile]
    // B x4: row = ((lane & 16) >> 1) + (lane & 7), col8 = (lane >> 3) & 1
    const uint32_t a_off = (uint32_t)((lane & 15) * ROWB + (lane >> 4) * 16);
    const uint32_t b_off = (uint32_t)((((lane & 16) >> 1) + (lane & 7)) * ROWB +
                                      (((lane >> 3) & 1) * 16));

    auto load_stage = [&](int s, int c) {
        char* stage = smem + s * STAGEB;
        #pragma unroll
        for (int it = 0; it < 8; it++) {
            int u = tid + it * 256;          // 0..2047
            int t = u >> 9;                  // tile 0..3
            int rem = u & 511;
            int r = rem >> 2;
            int g = rem & 3;
            const __nv_bfloat16* src;
            int grow;
            if (t == 0)      { src = Ahi; grow = row0 + r; }
            else if (t == 1) { src = Alo; grow = row0 + r; }
            else if (t == 2) { src = Bhi; grow = col0 + r; }
            else             { src = Blo; grow = col0 + r; }
            uint4 val = *(const uint4*)(src + (size_t)grow * EMBED + c * KC + g * 8);
            *(uint4*)(stage + t * TILEB + r * ROWB + g * 16) = val;
        }
    };

    load_stage(0, 0);
    __syncthreads();

    for (int c = 0; c < NCH; c++) {
        const int s = c & 1;
        if (c + 1 < NCH) load_stage(s ^ 1, c + 1);

        const uint32_t st = sbase + s * STAGEB;
        #pragma unroll
        for (int ks = 0; ks < 2; ks++) {
            const uint32_t kb = (uint32_t)(ks * 32);  // 16 bf16 = 32 bytes
            uint32_t ah[4][4], al[4][4];
            uint32_t bh[4][2], bl[4][2];
            #pragma unroll
            for (int mt = 0; mt < 4; mt++) {
                uint32_t ra = st + (uint32_t)((wm * 64 + mt * 16) * ROWB) + kb + a_off;
                ldsm4(ah[mt], ra);                     // tile 0 = Ahi
                ldsm4(al[mt], ra + TILEB);             // tile 1 = Alo
            }
            #pragma unroll
            for (int np = 0; np < 2; np++) {           // pairs of n-tiles
                uint32_t rb = st + 2 * TILEB +
                              (uint32_t)((wn * 32 + np * 16) * ROWB) + kb + b_off;
                uint32_t rh[4], rl[4];
                ldsm4(rh, rb);                         // tile 2 = Bhi
                ldsm4(rl, rb + TILEB);                 // tile 3 = Blo
                bh[2 * np][0] = rh[0]; bh[2 * np][1] = rh[1];
                bh[2 * np + 1][0] = rh[2]; bh[2 * np + 1][1] = rh[3];
                bl[2 * np][0] = rl[0]; bl[2 * np][1] = rl[1];
                bl[2 * np + 1][0] = rl[2]; bl[2 * np + 1][1] = rl[3];
            }
            #pragma unroll
            for (int mt = 0; mt < 4; mt++)
                #pragma unroll
                for (int nt = 0; nt < 4; nt++) {
                    mma16816(acc[mt][nt], ah[mt], bh[nt][0], bh[nt][1]);
                    mma16816(acc[mt][nt], ah[mt], bl[nt][0], bl[nt][1]);
                    mma16816(acc[mt][nt], al[mt], bh[nt][0], bh[nt][1]);
                }
        }
        __syncthreads();
    }

    // Epilogue: direct global stores (float2 per (mt,nt) per half)
    #pragma unroll
    for (int mt = 0; mt < 4; mt++) {
        int r0 = row0 + wm * 64 + mt * 16 + (lane >> 2);
        #pragma unroll
        for (int nt = 0; nt < 4; nt++) {
            int mcol = col0 + wn * 32 + nt * 8 + 2 * (lane & 3);
            float b0 = bias[mcol], b1 = bias[mcol + 1];
            float2 v0, v1;
            v0.x = (acc[mt][nt][0] + b0) * scale;
            v0.y = (acc[mt][nt][1] + b1) * scale;
            v1.x = (acc[mt][nt][2] + b0) * scale;
            v1.y = (acc[mt][nt][3] + b1) * scale;
            *(float2*)(Y + (size_t)r0 * EMBED + mcol) = v0;
            *(float2*)(Y + (size_t)(r0 + 8) * EMBED + mcol) = v1;
        }
    }
}

// ---------------------------------------------------------------------------
// Attention kernel: one block per (col c, head h). (unchanged from R1)
// ---------------------------------------------------------------------------
__global__ __launch_bounds__(256) void attn_kernel(
    const float* __restrict__ gq, const float* __restrict__ gk,
    const float* __restrict__ gv, const unsigned char* __restrict__ mask,
    float* __restrict__ probs, float* __restrict__ cout, int write_probs)
{
    extern __shared__ float sm[];
    float* qT = sm;                        // 64*129
    float* kT = qT + 64 * 129;             // 64*129
    float* vS = kT + 64 * 129;             // 128*68
    float* S  = vS + 128 * 68;             // 128*129
    unsigned char* mk = (unsigned char*)(S + 128 * 129);

    const int c = blockIdx.x;
    const int h = blockIdx.y;
    const int t = threadIdx.x;
    const int tx = t & 15;
    const int ty = t >> 4;

    const size_t base = (size_t)c * EMBED + h * DKK;

    for (int idx = t; idx < RDIM * DKK; idx += 256) {
        int i = idx >> 6;
        int d = idx & 63;
        size_t g = (size_t)i * (CDIM * EMBED) + base + d;
        qT[d * 129 + i] = gq[g];
        kT[d * 129 + i] = gk[g];
        vS[i * 68 + d]  = gv[g];
    }
    if (t < RDIM) mk[t] = mask[(size_t)t * CDIM + c];
    __syncthreads();

    {
        const int i0 = ty * 8;
        const int j0 = tx * 8;
        float acc[8][8];
        #pragma unroll
        for (int i = 0; i < 8; i++)
            #pragma unroll
            for (int j = 0; j < 8; j++) acc[i][j] = 0.f;

        for (int d = 0; d < DKK; d++) {
            float qr[8], kr[8];
            #pragma unroll
            for (int u = 0; u < 8; u++) qr[u] = qT[d * 129 + i0 + u];
            #pragma unroll
            for (int u = 0; u < 8; u++) kr[u] = kT[d * 129 + j0 + u];
            #pragma unroll
            for (int i = 0; i < 8; i++)
                #pragma unroll
                for (int j = 0; j < 8; j++)
                    acc[i][j] += qr[i] * kr[j];
        }
        #pragma unroll
        for (int i = 0; i < 8; i++)
            #pragma unroll
            for (int j = 0; j < 8; j++)
                S[(i0 + i) * 129 + (j0 + j)] = acc[i][j];
    }
    __syncthreads();

    {
        const int warp = t >> 5;
        const int lane = t & 31;
        for (int r = 0; r < 16; r++) {
            int i = warp * 16 + r;
            float vals[4];
            float mx = -1e30f;
            #pragma unroll
            for (int u = 0; u < 4; u++) {
                int j = lane + 32 * u;
                float s = S[i * 129 + j];
                if (mk[j]) s = -10000.f;
                vals[u] = s;
                mx = fmaxf(mx, s);
            }
            #pragma unroll
            for (int o = 16; o > 0; o >>= 1)
                mx = fmaxf(mx, __shfl_xor_sync(0xffffffffu, mx, o));
            float sum = 0.f;
            #pragma unroll
            for (int u = 0; u < 4; u++) {
                vals[u] = __expf(vals[u] - mx);
                sum += vals[u];
            }
            #pragma unroll
            for (int o = 16; o > 0; o >>= 1)
                sum += __shfl_xor_sync(0xffffffffu, sum, o);
            float inv = 1.f / sum;
            size_t pb = ((size_t)(h * CDIM + c) * RDIM + i) * RDIM;
            #pragma unroll
            for (int u = 0; u < 4; u++) {
                int j = lane + 32 * u;
                float p = vals[u] * inv;
                S[i * 129 + j] = p;
                if (write_probs) probs[pb + j] = p;
            }
        }
    }
    __syncthreads();

    {
        const int i0 = ty * 8;
        const int d0 = tx * 4;
        float acc[8][4];
        #pragma unroll
        for (int i = 0; i < 8; i++)
            #pragma unroll
            for (int d = 0; d < 4; d++) acc[i][d] = 0.f;

        for (int j = 0; j < RDIM; j++) {
            float4 vv = *(const float4*)(vS + j * 68 + d0);
            float vr[4] = {vv.x, vv.y, vv.z, vv.w};
            #pragma unroll
            for (int i = 0; i < 8; i++) {
                float p = S[(i0 + i) * 129 + j];
                #pragma unroll
                for (int d = 0; d < 4; d++)
                    acc[i][d] += p * vr[d];
            }
        }
        #pragma unroll
        for (int i = 0; i < 8; i++) {
            float4 r = make_float4(acc[i][0], acc[i][1], acc[i][2], acc[i][3]);
            *(float4*)(cout + (size_t)(i0 + i) * (CDIM * EMBED) + base + d0) = r;
        }
    }
}

// ---------------------------------------------------------------------------
extern "C" void kernel_launch(void* const* d_in, const int* in_sizes, int n_in,
                              void* d_out, int out_size)
{
    const float* x  = (const float*)d_in[0];
    const unsigned char* mask = (const unsigned char*)d_in[1];
    const float* Wq = (const float*)d_in[2];
    const float* bq = (const float*)d_in[3];
    const float* Wk = (const float*)d_in[4];
    const float* bk = (const float*)d_in[5];
    const float* Wv = (const float*)d_in[6];
    const float* bv = (const float*)d_in[7];
    const float* Wo = (const float*)d_in[8];
    const float* bo = (const float*)d_in[9];
    float* out = (float*)d_out;

    float *q, *k, *v;
    __nv_bfloat16 *ahi, *alo, *whi, *wlo;
    cudaGetSymbolAddress((void**)&q, g_q);
    cudaGetSymbolAddress((void**)&k, g_k);
    cudaGetSymbolAddress((void**)&v, g_v);
    cudaGetSymbolAddress((void**)&ahi, g_ahi);
    cudaGetSymbolAddress((void**)&alo, g_alo);
    cudaGetSymbolAddress((void**)&whi, g_whi);
    cudaGetSymbolAddress((void**)&wlo, g_wlo);

    const long long out_elems = (long long)NTOK * EMBED;
    const long long probs_elems = (long long)HEADS * CDIM * RDIM * RDIM;
    int write_probs = ((long long)out_size >= out_elems + probs_elems) ? 1 : 0;
    float* probs = write_probs ? (out + out_elems) : nullptr;

    const int attn_smem = (64 * 129 * 2 + 128 * 68 + 128 * 129) * 4 + 128;
    cudaFuncSetAttribute(attn_kernel, cudaFuncAttributeMaxDynamicSharedMemorySize,
                         attn_smem);
    const int gemm_smem = 2 * STAGEB;   // 81920 B
    cudaFuncSetAttribute(mma_gemm, cudaFuncAttributeMaxDynamicSharedMemorySize,
                         gemm_smem);

    const size_t WSZ = (size_t)EMBED * EMBED;
    const int xn4 = (int)(((size_t)NTOK * EMBED) / 4);
    const int wn4 = (int)(WSZ / 4);

    split_kernel<<<(xn4 + 255) / 256, 256>>>((const float4*)x, ahi, alo, xn4);
    split_kernel<<<(wn4 + 255) / 256, 256>>>((const float4*)Wq, whi + 0 * WSZ, wlo + 0 * WSZ, wn4);
    split_kernel<<<(wn4 + 255) / 256, 256>>>((const float4*)Wk, whi + 1 * WSZ, wlo + 1 * WSZ, wn4);
    split_kernel<<<(wn4 + 255) / 256, 256>>>((const float4*)Wv, whi + 2 * WSZ, wlo + 2 * WSZ, wn4);
    split_kernel<<<(wn4 + 255) / 256, 256>>>((const float4*)Wo, whi + 3 * WSZ, wlo + 3 * WSZ, wn4);

    dim3 ggrid(NTOK / 128, EMBED / 128);   // (256, 6)
    const float scaling = 0.125f;          // DK^-0.5

    mma_gemm<<<ggrid, 256, gemm_smem>>>(ahi, alo, whi + 0 * WSZ, wlo + 0 * WSZ, bq, q, scaling);
    mma_gemm<<<ggrid, 256, gemm_smem>>>(ahi, alo, whi + 1 * WSZ, wlo + 1 * WSZ, bk, k, 1.f);
    mma_gemm<<<ggrid, 256, gemm_smem>>>(ahi, alo, whi + 2 * WSZ, wlo + 2 * WSZ, bv, v, 1.f);

    dim3 agrid(CDIM, HEADS);               // (256, 12)
    attn_kernel<<<agrid, 256, attn_smem>>>(q, k, v, mask, probs, q, write_probs);

    split_kernel<<<(xn4 + 255) / 256, 256>>>((const float4*)q, ahi, alo, xn4);
    mma_gemm<<<ggrid, 256, gemm_smem>>>(ahi, alo, whi + 3 * WSZ, wlo + 3 * WSZ, bo, out, 1.f);
}

// round 5
// speedup vs baseline: 3.0769x; 1.7681x over previous
#include <cuda_runtime.h>
#include <cuda_bf16.h>
#include <cstdint>

#define EMBED 768
#define HEADS 12
#define DKK   64
#define RDIM  128
#define CDIM  256
#define NTOK  (RDIM * CDIM)   // 32768

typedef __nv_bfloat16 bf16;
typedef __nv_bfloat162 bf162;

// ---------------------------------------------------------------------------
// Scratch (allocation-free rule: __device__ globals).
// x splits double as context splits after the QKV GEMMs consume them.
// ---------------------------------------------------------------------------
__device__ bf16 g_xhi[(size_t)NTOK * EMBED];
__device__ bf16 g_xlo[(size_t)NTOK * EMBED];
__device__ bf16 g_qhi[(size_t)NTOK * EMBED];
__device__ bf16 g_qlo[(size_t)NTOK * EMBED];
__device__ bf16 g_khi[(size_t)NTOK * EMBED];
__device__ bf16 g_klo[(size_t)NTOK * EMBED];
__device__ bf16 g_vhi[(size_t)NTOK * EMBED];
__device__ bf16 g_vlo[(size_t)NTOK * EMBED];
__device__ bf16 g_whi[4 * (size_t)EMBED * EMBED];
__device__ bf16 g_wlo[4 * (size_t)EMBED * EMBED];

__device__ __forceinline__ uint32_t smem_u32(const void* p) {
    uint32_t a;
    asm("{ .reg .u64 t; cvta.to.shared.u64 t, %1; cvt.u32.u64 %0, t; }"
        : "=r"(a) : "l"(p));
    return a;
}

__device__ __forceinline__ void ldsm4(uint32_t (&r)[4], uint32_t addr) {
    asm volatile("ldmatrix.sync.aligned.m8n8.x4.shared.b16 {%0,%1,%2,%3}, [%4];"
                 : "=r"(r[0]), "=r"(r[1]), "=r"(r[2]), "=r"(r[3]) : "r"(addr));
}

__device__ __forceinline__ void ldsm4t(uint32_t (&r)[4], uint32_t addr) {
    asm volatile("ldmatrix.sync.aligned.m8n8.x4.trans.shared.b16 {%0,%1,%2,%3}, [%4];"
                 : "=r"(r[0]), "=r"(r[1]), "=r"(r[2]), "=r"(r[3]) : "r"(addr));
}

__device__ __forceinline__ void mma16816(float (&c)[4], const uint32_t (&a)[4],
                                         uint32_t b0, uint32_t b1) {
    asm volatile(
        "mma.sync.aligned.m16n8k16.row.col.f32.bf16.bf16.f32 "
        "{%0,%1,%2,%3}, {%4,%5,%6,%7}, {%8,%9}, {%0,%1,%2,%3};"
        : "+f"(c[0]), "+f"(c[1]), "+f"(c[2]), "+f"(c[3])
        : "r"(a[0]), "r"(a[1]), "r"(a[2]), "r"(a[3]), "r"(b0), "r"(b1));
}

#define CP_ASYNC16(dst, src) \
    asm volatile("cp.async.cg.shared.global [%0], [%1], 16;" \
                 :: "r"(dst), "l"(src))
#define CP_COMMIT() asm volatile("cp.async.commit_group;" ::: "memory")
#define CP_WAIT0()  asm volatile("cp.async.wait_group 0;" ::: "memory")

// ---------------------------------------------------------------------------
// split fp32 -> (hi bf16, lo bf16), vectorized by 4
// ---------------------------------------------------------------------------
__global__ __launch_bounds__(256) void split_kernel(
    const float4* __restrict__ src, bf16* __restrict__ hi,
    bf16* __restrict__ lo, int n4)
{
    int i = blockIdx.x * blockDim.x + threadIdx.x;
    if (i >= n4) return;
    float4 v = src[i];
    bf16 h0 = __float2bfloat16(v.x);
    bf16 h1 = __float2bfloat16(v.y);
    bf16 h2 = __float2bfloat16(v.z);
    bf16 h3 = __float2bfloat16(v.w);
    bf16 l0 = __float2bfloat16(v.x - __bfloat162float(h0));
    bf16 l1 = __float2bfloat16(v.y - __bfloat162float(h1));
    bf16 l2 = __float2bfloat16(v.z - __bfloat162float(h2));
    bf16 l3 = __float2bfloat16(v.w - __bfloat162float(h3));
    bf162* hp = (bf162*)(hi + (size_t)i * 4);
    bf162* lp = (bf162*)(lo + (size_t)i * 4);
    hp[0] = bf162(h0, h1);
    hp[1] = bf162(h2, h3);
    lp[0] = bf162(l0, l1);
    lp[1] = bf162(l2, l3);
}

// ---------------------------------------------------------------------------
// mma.sync split-bf16 GEMM: Y[n,m] = (sum_k A[n,k]*W[m,k] + bias[m]) * scale
// MODE 0: write f32 to Yf.  MODE 1: write bf16 hi/lo split to Yhi/Ylo.
// CTA 128x128, 8 warps, K-chunk 32, cp.async double-buffered smem.
// ---------------------------------------------------------------------------
#define KC      32
#define NCH     (EMBED / KC)          // 24
#define ROWB    80
#define TILEB   (128 * ROWB)          // 10240 B
#define STAGEB  (4 * TILEB)

template<int MODE>
__global__ __launch_bounds__(256) void mma_gemm(
    const bf16* __restrict__ Ahi, const bf16* __restrict__ Alo,
    const bf16* __restrict__ Bhi, const bf16* __restrict__ Blo,
    const float* __restrict__ bias, float* __restrict__ Yf,
    bf16* __restrict__ Yhi, bf16* __restrict__ Ylo, float scale)
{
    extern __shared__ char smem[];
    const uint32_t sbase = smem_u32(smem);

    const int tid  = threadIdx.x;
    const int wid  = tid >> 5;
    const int lane = tid & 31;
    const int wm   = wid >> 2;
    const int wn   = wid & 3;
    const int row0 = blockIdx.x * 128;
    const int col0 = blockIdx.y * 128;

    float acc[4][4][4];
    #pragma unroll
    for (int mt = 0; mt < 4; mt++)
        #pragma unroll
        for (int nt = 0; nt < 4; nt++)
            #pragma unroll
            for (int u = 0; u < 4; u++) acc[mt][nt][u] = 0.f;

    const uint32_t a_off = (uint32_t)((lane & 15) * ROWB + (lane >> 4) * 16);
    const uint32_t b_off = (uint32_t)((((lane & 16) >> 1) + (lane & 7)) * ROWB +
                                      (((lane >> 3) & 1) * 16));

    auto load_stage = [&](int s, int c) {
        uint32_t stage = sbase + s * STAGEB;
        #pragma unroll
        for (int it = 0; it < 8; it++) {
            int u = tid + it * 256;
            int t = u >> 9;
            int rem = u & 511;
            int r = rem >> 2;
            int g = rem & 3;
            const bf16* src;
            int grow;
            if (t == 0)      { src = Ahi; grow = row0 + r; }
            else if (t == 1) { src = Alo; grow = row0 + r; }
            else if (t == 2) { src = Bhi; grow = col0 + r; }
            else             { src = Blo; grow = col0 + r; }
            CP_ASYNC16(stage + (uint32_t)(t * TILEB + r * ROWB + g * 16),
                       src + (size_t)grow * EMBED + c * KC + g * 8);
        }
    };

    load_stage(0, 0);
    CP_COMMIT();

    for (int c = 0; c < NCH; c++) {
        const int s = c & 1;
        CP_WAIT0();
        __syncthreads();
        if (c + 1 < NCH) { load_stage(s ^ 1, c + 1); CP_COMMIT(); }

        const uint32_t st = sbase + s * STAGEB;
        #pragma unroll
        for (int ks = 0; ks < 2; ks++) {
            const uint32_t kb = (uint32_t)(ks * 32);
            uint32_t ah[4][4], al[4][4];
            uint32_t bh[4][2], bl[4][2];
            #pragma unroll
            for (int mt = 0; mt < 4; mt++) {
                uint32_t ra = st + (uint32_t)((wm * 64 + mt * 16) * ROWB) + kb + a_off;
                ldsm4(ah[mt], ra);
                ldsm4(al[mt], ra + TILEB);
            }
            #pragma unroll
            for (int np = 0; np < 2; np++) {
                uint32_t rb = st + 2 * TILEB +
                              (uint32_t)((wn * 32 + np * 16) * ROWB) + kb + b_off;
                uint32_t rh[4], rl[4];
                ldsm4(rh, rb);
                ldsm4(rl, rb + TILEB);
                bh[2 * np][0] = rh[0]; bh[2 * np][1] = rh[1];
                bh[2 * np + 1][0] = rh[2]; bh[2 * np + 1][1] = rh[3];
                bl[2 * np][0] = rl[0]; bl[2 * np][1] = rl[1];
                bl[2 * np + 1][0] = rl[2]; bl[2 * np + 1][1] = rl[3];
            }
            #pragma unroll
            for (int mt = 0; mt < 4; mt++)
                #pragma unroll
                for (int nt = 0; nt < 4; nt++) {
                    mma16816(acc[mt][nt], ah[mt], bh[nt][0], bh[nt][1]);
                    mma16816(acc[mt][nt], ah[mt], bl[nt][0], bl[nt][1]);
                    mma16816(acc[mt][nt], al[mt], bh[nt][0], bh[nt][1]);
                }
        }
    }

    #pragma unroll
    for (int mt = 0; mt < 4; mt++) {
        int r0 = row0 + wm * 64 + mt * 16 + (lane >> 2);
        #pragma unroll
        for (int nt = 0; nt < 4; nt++) {
            int mcol = col0 + wn * 32 + nt * 8 + 2 * (lane & 3);
            float b0 = bias[mcol], b1 = bias[mcol + 1];
            float o0 = (acc[mt][nt][0] + b0) * scale;
            float o1 = (acc[mt][nt][1] + b1) * scale;
            float o2 = (acc[mt][nt][2] + b0) * scale;
            float o3 = (acc[mt][nt][3] + b1) * scale;
            if (MODE == 0) {
                *(float2*)(Yf + (size_t)r0 * EMBED + mcol) = make_float2(o0, o1);
                *(float2*)(Yf + (size_t)(r0 + 8) * EMBED + mcol) = make_float2(o2, o3);
            } else {
                bf16 h0 = __float2bfloat16(o0), h1 = __float2bfloat16(o1);
                bf16 h2 = __float2bfloat16(o2), h3 = __float2bfloat16(o3);
                *(bf162*)(Yhi + (size_t)r0 * EMBED + mcol) = bf162(h0, h1);
                *(bf162*)(Yhi + (size_t)(r0 + 8) * EMBED + mcol) = bf162(h2, h3);
                bf16 l0 = __float2bfloat16(o0 - __bfloat162float(h0));
                bf16 l1 = __float2bfloat16(o1 - __bfloat162float(h1));
                bf16 l2 = __float2bfloat16(o2 - __bfloat162float(h2));
                bf16 l3 = __float2bfloat16(o3 - __bfloat162float(h3));
                *(bf162*)(Ylo + (size_t)r0 * EMBED + mcol) = bf162(l0, l1);
                *(bf162*)(Ylo + (size_t)(r0 + 8) * EMBED + mcol) = bf162(l2, l3);
            }
        }
    }
}

// ---------------------------------------------------------------------------
// Attention via mma.sync. One block per (c, h); 8 warps; warp owns 16 i-rows.
// smem (swizzled SW128-style, no padding):
//   Qhi 0, Qlo 16K, Khi 32K, Klo 48K, Vhi 64K, Vlo 80K   (128x64 bf16 each)
//   Phi 96K, Plo 128K                                     (128x128 bf16 each)
//   mask bitwords @160K
// ---------------------------------------------------------------------------
#define AT_QHI 0
#define AT_QLO 16384
#define AT_KHI 32768
#define AT_KLO 49152
#define AT_VHI 65536
#define AT_VLO 81920
#define AT_PHI 98304
#define AT_PLO 131072
#define AT_MKW 163840
#define AT_SMEM (163840 + 32)

__device__ __forceinline__ uint32_t qswz(int r, int c) {
    return (uint32_t)(r * 128 + ((c ^ (r & 7)) * 16));
}
__device__ __forceinline__ uint32_t pswz(int r, int c) {
    return (uint32_t)(r * 256 + (((c & 8) | ((c & 7) ^ (r & 7))) * 16));
}

__global__ __launch_bounds__(256) void attn_mma(
    const bf16* __restrict__ qhi, const bf16* __restrict__ qlo,
    const bf16* __restrict__ khi, const bf16* __restrict__ klo,
    const bf16* __restrict__ vhi, const bf16* __restrict__ vlo,
    const unsigned char* __restrict__ mask, float* __restrict__ probs,
    bf16* __restrict__ chi, bf16* __restrict__ clo, int write_probs)
{
    extern __shared__ char smc[];
    const uint32_t sb = smem_u32(smc);

    const int c = blockIdx.x;
    const int h = blockIdx.y;
    const int tid = threadIdx.x;
    const int wid = tid >> 5;
    const int lane = tid & 31;
    const size_t base = (size_t)c * EMBED + h * DKK;

    // ---- load Q/K/V hi/lo tiles via cp.async ----
    {
        const bf16* srcs[6] = { qhi, qlo, khi, klo, vhi, vlo };
        #pragma unroll
        for (int t = 0; t < 6; t++) {
            #pragma unroll
            for (int it = 0; it < 4; it++) {
                int e = tid + it * 256;          // 0..1023
                int r = e >> 3;
                int ch = e & 7;
                CP_ASYNC16(sb + (uint32_t)(t * 16384) + qswz(r, ch),
                           srcs[t] + (size_t)r * (CDIM * EMBED) + base + ch * 8);
            }
        }
        CP_COMMIT();
    }
    if (tid < 4) {
        uint32_t w = 0;
        for (int b = 0; b < 32; b++)
            if (mask[(size_t)(tid * 32 + b) * CDIM + c]) w |= (1u << b);
        *(uint32_t*)(smc + AT_MKW + tid * 4) = w;
    }
    CP_WAIT0();
    __syncthreads();

    const int i0 = wid * 16;

    // ---- S = Q*K^T, 3-pass split, warp owns rows [i0, i0+16), all 128 cols
    float acc[16][4];
    #pragma unroll
    for (int nt = 0; nt < 16; nt++)
        #pragma unroll
        for (int u = 0; u < 4; u++) acc[nt][u] = 0.f;

    #pragma unroll
    for (int ks = 0; ks < 4; ks++) {
        uint32_t ah[4], al[4];
        {
            int rr = i0 + (lane & 15);
            int cc = 2 * ks + (lane >> 4);
            uint32_t ad = sb + AT_QHI + qswz(rr, cc);
            ldsm4(ah, ad);
            ldsm4(al, ad + 16384);
        }
        #pragma unroll
        for (int jg = 0; jg < 8; jg++) {
            int jr = jg * 16 + ((lane & 16) >> 1) + (lane & 7);
            int cc = 2 * ks + ((lane >> 3) & 1);
            uint32_t bd = sb + AT_KHI + qswz(jr, cc);
            uint32_t bh[4], bl[4];
            ldsm4(bh, bd);
            ldsm4(bl, bd + 16384);
            mma16816(acc[2 * jg], ah, bh[0], bh[1]);
            mma16816(acc[2 * jg], ah, bl[0], bl[1]);
            mma16816(acc[2 * jg], al, bh[0], bh[1]);
            mma16816(acc[2 * jg + 1], ah, bh[2], bh[3]);
            mma16816(acc[2 * jg + 1], ah, bl[2], bl[3]);
            mma16816(acc[2 * jg + 1], al, bh[2], bh[3]);
        }
    }

    // ---- mask + softmax (rows i0 + lane>>2 and +8) ----
    {
        uint32_t mw[4];
        #pragma unroll
        for (int u = 0; u < 4; u++) mw[u] = *(const uint32_t*)(smc + AT_MKW + u * 4);
        const int jb = (lane & 3) * 2;

        float mxl = -1e30f, mxh = -1e30f;
        #pragma unroll
        for (int nt = 0; nt < 16; nt++) {
            int j0 = nt * 8 + jb;
            bool m0 = (mw[j0 >> 5] >> (j0 & 31)) & 1;
            bool m1 = (mw[j0 >> 5] >> ((j0 + 1) & 31)) & 1;
            if (m0) { acc[nt][0] = -10000.f; acc[nt][2] = -10000.f; }
            if (m1) { acc[nt][1] = -10000.f; acc[nt][3] = -10000.f; }
            mxl = fmaxf(mxl, fmaxf(acc[nt][0], acc[nt][1]));
            mxh = fmaxf(mxh, fmaxf(acc[nt][2], acc[nt][3]));
        }
        #pragma unroll
        for (int o = 1; o <= 2; o <<= 1) {
            mxl = fmaxf(mxl, __shfl_xor_sync(0xffffffffu, mxl, o));
            mxh = fmaxf(mxh, __shfl_xor_sync(0xffffffffu, mxh, o));
        }
        float sl = 0.f, sh = 0.f;
        #pragma unroll
        for (int nt = 0; nt < 16; nt++) {
            acc[nt][0] = __expf(acc[nt][0] - mxl);
            acc[nt][1] = __expf(acc[nt][1] - mxl);
            acc[nt][2] = __expf(acc[nt][2] - mxh);
            acc[nt][3] = __expf(acc[nt][3] - mxh);
            sl += acc[nt][0] + acc[nt][1];
            sh += acc[nt][2] + acc[nt][3];
        }
        #pragma unroll
        for (int o = 1; o <= 2; o <<= 1) {
            sl += __shfl_xor_sync(0xffffffffu, sl, o);
            sh += __shfl_xor_sync(0xffffffffu, sh, o);
        }
        float il = 1.f / sl, ih = 1.f / sh;

        const int rl = i0 + (lane >> 2);
        #pragma unroll
        for (int nt = 0; nt < 16; nt++) {
            float p0 = acc[nt][0] * il;
            float p1 = acc[nt][1] * il;
            float p2 = acc[nt][2] * ih;
            float p3 = acc[nt][3] * ih;
            bf16 h0 = __float2bfloat16(p0), h1 = __float2bfloat16(p1);
            bf16 h2 = __float2bfloat16(p2), h3 = __float2bfloat16(p3);
            uint32_t a0 = pswz(rl, nt) + (uint32_t)(jb * 2);
            uint32_t a1 = pswz(rl + 8, nt) + (uint32_t)(jb * 2);
            *(bf162*)(smc + AT_PHI + a0) = bf162(h0, h1);
            *(bf162*)(smc + AT_PHI + a1) = bf162(h2, h3);
            bf16 l0 = __float2bfloat16(p0 - __bfloat162float(h0));
            bf16 l1 = __float2bfloat16(p1 - __bfloat162float(h1));
            bf16 l2 = __float2bfloat16(p2 - __bfloat162float(h2));
            bf16 l3 = __float2bfloat16(p3 - __bfloat162float(h3));
            *(bf162*)(smc + AT_PLO + a0) = bf162(l0, l1);
            *(bf162*)(smc + AT_PLO + a1) = bf162(l2, l3);
        }
    }
    __syncthreads();

    // ---- probs out (coalesced, reconstruct hi+lo) ----
    if (write_probs) {
        const size_t pb = ((size_t)(h * CDIM + c) * RDIM) * RDIM;
        #pragma unroll
        for (int it = 0; it < 16; it++) {
            int e = tid + it * 256;          // float4 index 0..4095
            int r = e >> 5;
            int s2 = e & 31;
            uint32_t pa = pswz(r, s2 >> 1) + (uint32_t)((s2 & 1) * 8);
            uint2 uh = *(const uint2*)(smc + AT_PHI + pa);
            uint2 ul = *(const uint2*)(smc + AT_PLO + pa);
            bf162 h0 = *(bf162*)&uh.x, h1 = *(bf162*)&uh.y;
            bf162 l0 = *(bf162*)&ul.x, l1 = *(bf162*)&ul.y;
            float4 o;
            o.x = __bfloat162float(h0.x) + __bfloat162float(l0.x);
            o.y = __bfloat162float(h0.y) + __bfloat162float(l0.y);
            o.z = __bfloat162float(h1.x) + __bfloat162float(l1.x);
            o.w = __bfloat162float(h1.y) + __bfloat162float(l1.y);
            *(float4*)(probs + pb + (size_t)r * RDIM + s2 * 4) = o;
        }
    }

    // ---- C = P*V, 3-pass split ----
    float acc2[8][4];
    #pragma unroll
    for (int nt = 0; nt < 8; nt++)
        #pragma unroll
        for (int u = 0; u < 4; u++) acc2[nt][u] = 0.f;

    #pragma unroll
    for (int j16 = 0; j16 < 8; j16++) {
        uint32_t ph4[4], pl4[4];
        {
            int rr = i0 + (lane & 15);
            int cc = 2 * j16 + (lane >> 4);
            uint32_t ad = sb + AT_PHI + pswz(rr, cc);
            ldsm4(ph4, ad);
            ldsm4(pl4, ad + 32768);
        }
        #pragma unroll
        for (int dg = 0; dg < 4; dg++) {
            int jr = j16 * 16 + (lane & 7) + ((lane >> 3) & 1) * 8;
            int cc = 2 * dg + (lane >> 4);
            uint32_t vd = sb + AT_VHI + qswz(jr, cc);
            uint32_t vh4[4], vl4[4];
            ldsm4t(vh4, vd);
            ldsm4t(vl4, vd + 16384);
            mma16816(acc2[2 * dg], ph4, vh4[0], vh4[1]);
            mma16816(acc2[2 * dg], ph4, vl4[0], vl4[1]);
            mma16816(acc2[2 * dg], pl4, vh4[0], vh4[1]);
            mma16816(acc2[2 * dg + 1], ph4, vh4[2], vh4[3]);
            mma16816(acc2[2 * dg + 1], ph4, vl4[2], vl4[3]);
            mma16816(acc2[2 * dg + 1], pl4, vh4[2], vh4[3]);
        }
    }

    // ---- context epilogue: split to hi/lo bf16, scattered 4B stores ----
    {
        const int r0 = i0 + (lane >> 2);
        #pragma unroll
        for (int nt = 0; nt < 8; nt++) {
            int d0 = nt * 8 + (lane & 3) * 2;
            float o0 = acc2[nt][0], o1 = acc2[nt][1];
            float o2 = acc2[nt][2], o3 = acc2[nt][3];
            bf16 h0 = __float2bfloat16(o0), h1 = __float2bfloat16(o1);
            bf16 h2 = __float2bfloat16(o2), h3 = __float2bfloat16(o3);
            size_t g0 = (size_t)r0 * (CDIM * EMBED) + base + d0;
            size_t g1 = (size_t)(r0 + 8) * (CDIM * EMBED) + base + d0;
            *(bf162*)(chi + g0) = bf162(h0, h1);
            *(bf162*)(chi + g1) = bf162(h2, h3);
            bf16 l0 = __float2bfloat16(o0 - __bfloat162float(h0));
            bf16 l1 = __float2bfloat16(o1 - __bfloat162float(h1));
            bf16 l2 = __float2bfloat16(o2 - __bfloat162float(h2));
            bf16 l3 = __float2bfloat16(o3 - __bfloat162float(h3));
            *(bf162*)(clo + g0) = bf162(l0, l1);
            *(bf162*)(clo + g1) = bf162(l2, l3);
        }
    }
}

// ---------------------------------------------------------------------------
extern "C" void kernel_launch(void* const* d_in, const int* in_sizes, int n_in,
                              void* d_out, int out_size)
{
    const float* x  = (const float*)d_in[0];
    const unsigned char* mask = (const unsigned char*)d_in[1];
    const float* Wq = (const float*)d_in[2];
    const float* bq = (const float*)d_in[3];
    const float* Wk = (const float*)d_in[4];
    const float* bk = (const float*)d_in[5];
    const float* Wv = (const float*)d_in[6];
    const float* bv = (const float*)d_in[7];
    const float* Wo = (const float*)d_in[8];
    const float* bo = (const float*)d_in[9];
    float* out = (float*)d_out;

    bf16 *xhi, *xlo, *qhi, *qlo, *khi, *klo, *vhi, *vlo, *whi, *wlo;
    cudaGetSymbolAddress((void**)&xhi, g_xhi);
    cudaGetSymbolAddress((void**)&xlo, g_xlo);
    cudaGetSymbolAddress((void**)&qhi, g_qhi);
    cudaGetSymbolAddress((void**)&qlo, g_qlo);
    cudaGetSymbolAddress((void**)&khi, g_khi);
    cudaGetSymbolAddress((void**)&klo, g_klo);
    cudaGetSymbolAddress((void**)&vhi, g_vhi);
    cudaGetSymbolAddress((void**)&vlo, g_vlo);
    cudaGetSymbolAddress((void**)&whi, g_whi);
    cudaGetSymbolAddress((void**)&wlo, g_wlo);

    const long long out_elems = (long long)NTOK * EMBED;
    const long long probs_elems = (long long)HEADS * CDIM * RDIM * RDIM;
    int write_probs = ((long long)out_size >= out_elems + probs_elems) ? 1 : 0;
    float* probs = write_probs ? (out + out_elems) : nullptr;

    const int gemm_smem = 2 * STAGEB;   // 81920
    cudaFuncSetAttribute(mma_gemm<0>, cudaFuncAttributeMaxDynamicSharedMemorySize, gemm_smem);
    cudaFuncSetAttribute(mma_gemm<1>, cudaFuncAttributeMaxDynamicSharedMemorySize, gemm_smem);
    cudaFuncSetAttribute(attn_mma, cudaFuncAttributeMaxDynamicSharedMemorySize, AT_SMEM);

    const size_t WSZ = (size_t)EMBED * EMBED;
    const int xn4 = (int)(((size_t)NTOK * EMBED) / 4);
    const int wn4 = (int)(WSZ / 4);

    split_kernel<<<(xn4 + 255) / 256, 256>>>((const float4*)x, xhi, xlo, xn4);
    split_kernel<<<(wn4 + 255) / 256, 256>>>((const float4*)Wq, whi + 0 * WSZ, wlo + 0 * WSZ, wn4);
    split_kernel<<<(wn4 + 255) / 256, 256>>>((const float4*)Wk, whi + 1 * WSZ, wlo + 1 * WSZ, wn4);
    split_kernel<<<(wn4 + 255) / 256, 256>>>((const float4*)Wv, whi + 2 * WSZ, wlo + 2 * WSZ, wn4);
    split_kernel<<<(wn4 + 255) / 256, 256>>>((const float4*)Wo, whi + 3 * WSZ, wlo + 3 * WSZ, wn4);

    dim3 ggrid(NTOK / 128, EMBED / 128);   // (256, 6)
    const float scaling = 0.125f;

    mma_gemm<1><<<ggrid, 256, gemm_smem>>>(xhi, xlo, whi + 0 * WSZ, wlo + 0 * WSZ,
                                           bq, nullptr, qhi, qlo, scaling);
    mma_gemm<1><<<ggrid, 256, gemm_smem>>>(xhi, xlo, whi + 1 * WSZ, wlo + 1 * WSZ,
                                           bk, nullptr, khi, klo, 1.f);
    mma_gemm<1><<<ggrid, 256, gemm_smem>>>(xhi, xlo, whi + 2 * WSZ, wlo + 2 * WSZ,
                                           bv, nullptr, vhi, vlo, 1.f);

    dim3 agrid(CDIM, HEADS);               // (256, 12)
    attn_mma<<<agrid, 256, AT_SMEM>>>(qhi, qlo, khi, klo, vhi, vlo,
                                      mask, probs, xhi, xlo, write_probs);

    mma_gemm<0><<<ggrid, 256, gemm_smem>>>(xhi, xlo, whi + 3 * WSZ, wlo + 3 * WSZ,
                                           bo, out, nullptr, nullptr, 1.f);
}

// round 7
// speedup vs baseline: 3.2557x; 1.0581x over previous
#include <cuda_runtime.h>
#include <cuda_bf16.h>
#include <cstdint>

#define EMBED 768
#define HEADS 12
#define DKK   64
#define RDIM  128
#define CDIM  256
#define NTOK  (RDIM * CDIM)   // 32768

typedef __nv_bfloat16 bf16;
typedef __nv_bfloat162 bf162;

// ---------------------------------------------------------------------------
// Scratch (allocation-free rule: __device__ globals).
// x splits double as context splits after the QKV GEMMs consume them.
// ---------------------------------------------------------------------------
__device__ bf16 g_xhi[(size_t)NTOK * EMBED];
__device__ bf16 g_xlo[(size_t)NTOK * EMBED];
__device__ bf16 g_qhi[(size_t)NTOK * EMBED];
__device__ bf16 g_qlo[(size_t)NTOK * EMBED];
__device__ bf16 g_khi[(size_t)NTOK * EMBED];
__device__ bf16 g_klo[(size_t)NTOK * EMBED];
__device__ bf16 g_vhi[(size_t)NTOK * EMBED];
__device__ bf16 g_vlo[(size_t)NTOK * EMBED];
__device__ bf16 g_whi[4 * (size_t)EMBED * EMBED];
__device__ bf16 g_wlo[4 * (size_t)EMBED * EMBED];

__device__ __forceinline__ uint32_t smem_u32(const void* p) {
    uint32_t a;
    asm("{ .reg .u64 t; cvta.to.shared.u64 t, %1; cvt.u32.u64 %0, t; }"
        : "=r"(a) : "l"(p));
    return a;
}

__device__ __forceinline__ void ldsm4(uint32_t (&r)[4], uint32_t addr) {
    asm volatile("ldmatrix.sync.aligned.m8n8.x4.shared.b16 {%0,%1,%2,%3}, [%4];"
                 : "=r"(r[0]), "=r"(r[1]), "=r"(r[2]), "=r"(r[3]) : "r"(addr));
}

__device__ __forceinline__ void ldsm4t(uint32_t (&r)[4], uint32_t addr) {
    asm volatile("ldmatrix.sync.aligned.m8n8.x4.trans.shared.b16 {%0,%1,%2,%3}, [%4];"
                 : "=r"(r[0]), "=r"(r[1]), "=r"(r[2]), "=r"(r[3]) : "r"(addr));
}

__device__ __forceinline__ void mma16816(float (&c)[4], const uint32_t (&a)[4],
                                         uint32_t b0, uint32_t b1) {
    asm volatile(
        "mma.sync.aligned.m16n8k16.row.col.f32.bf16.bf16.f32 "
        "{%0,%1,%2,%3}, {%4,%5,%6,%7}, {%8,%9}, {%0,%1,%2,%3};"
        : "+f"(c[0]), "+f"(c[1]), "+f"(c[2]), "+f"(c[3])
        : "r"(a[0]), "r"(a[1]), "r"(a[2]), "r"(a[3]), "r"(b0), "r"(b1));
}

#define CP_ASYNC16(dst, src) \
    asm volatile("cp.async.cg.shared.global [%0], [%1], 16;" \
                 :: "r"(dst), "l"(src))
#define CP_COMMIT() asm volatile("cp.async.commit_group;" ::: "memory")
#define CP_WAIT0()  asm volatile("cp.async.wait_group 0;" ::: "memory")

// ---------------------------------------------------------------------------
// split fp32 -> (hi bf16, lo bf16)
// ---------------------------------------------------------------------------
__device__ __forceinline__ void split4(const float4 v, bf162* hp, bf162* lp) {
    bf16 h0 = __float2bfloat16(v.x);
    bf16 h1 = __float2bfloat16(v.y);
    bf16 h2 = __float2bfloat16(v.z);
    bf16 h3 = __float2bfloat16(v.w);
    bf16 l0 = __float2bfloat16(v.x - __bfloat162float(h0));
    bf16 l1 = __float2bfloat16(v.y - __bfloat162float(h1));
    bf16 l2 = __float2bfloat16(v.z - __bfloat162float(h2));
    bf16 l3 = __float2bfloat16(v.w - __bfloat162float(h3));
    hp[0] = bf162(h0, h1);
    hp[1] = bf162(h2, h3);
    lp[0] = bf162(l0, l1);
    lp[1] = bf162(l2, l3);
}

__global__ __launch_bounds__(256) void split_kernel(
    const float4* __restrict__ src, bf16* __restrict__ hi,
    bf16* __restrict__ lo, int n4)
{
    int i = blockIdx.x * blockDim.x + threadIdx.x;
    if (i >= n4) return;
    split4(src[i], (bf162*)(hi + (size_t)i * 4), (bf162*)(lo + (size_t)i * 4));
}

// one launch for all 4 weight matrices; blockIdx.y selects the weight
__global__ __launch_bounds__(256) void split_w_kernel(
    const float4* __restrict__ w0, const float4* __restrict__ w1,
    const float4* __restrict__ w2, const float4* __restrict__ w3,
    bf16* __restrict__ hi, bf16* __restrict__ lo, int n4)
{
    int i = blockIdx.x * blockDim.x + threadIdx.x;
    if (i >= n4) return;
    const float4* src = (blockIdx.y == 0) ? w0 : (blockIdx.y == 1) ? w1 :
                        (blockIdx.y == 2) ? w2 : w3;
    size_t o = (size_t)blockIdx.y * n4 * 4 + (size_t)i * 4;
    split4(src[i], (bf162*)(hi + o), (bf162*)(lo + o));
}

// ---------------------------------------------------------------------------
// mma.sync split-bf16 GEMM mainloop (shared by both GEMM kernels).
// CTA 128x128, 8 warps, K-chunk 32, cp.async double-buffered smem.
// ---------------------------------------------------------------------------
#define KC      32
#define NCH     (EMBED / KC)          // 24
#define ROWB    80
#define TILEB   (128 * ROWB)          // 10240 B
#define STAGEB  (4 * TILEB)

__device__ __forceinline__ void gemm_mainloop(
    const bf16* __restrict__ Ahi, const bf16* __restrict__ Alo,
    const bf16* __restrict__ Bhi, const bf16* __restrict__ Blo,
    int row0, int col0, uint32_t sbase, float (&acc)[4][4][4])
{
    const int tid  = threadIdx.x;
    const int wid  = tid >> 5;
    const int lane = tid & 31;
    const int wm   = wid >> 2;
    const int wn   = wid & 3;

    const uint32_t a_off = (uint32_t)((lane & 15) * ROWB + (lane >> 4) * 16);
    const uint32_t b_off = (uint32_t)((((lane & 16) >> 1) + (lane & 7)) * ROWB +
                                      (((lane >> 3) & 1) * 16));

    auto load_stage = [&](int s, int c) {
        uint32_t stage = sbase + s * STAGEB;
        #pragma unroll
        for (int it = 0; it < 8; it++) {
            int u = tid + it * 256;
            int t = u >> 9;
            int rem = u & 511;
            int r = rem >> 2;
            int g = rem & 3;
            const bf16* src;
            int grow;
            if (t == 0)      { src = Ahi; grow = row0 + r; }
            else if (t == 1) { src = Alo; grow = row0 + r; }
            else if (t == 2) { src = Bhi; grow = col0 + r; }
            else             { src = Blo; grow = col0 + r; }
            CP_ASYNC16(stage + (uint32_t)(t * TILEB + r * ROWB + g * 16),
                       src + (size_t)grow * EMBED + c * KC + g * 8);
        }
    };

    load_stage(0, 0);
    CP_COMMIT();

    for (int c = 0; c < NCH; c++) {
        const int s = c & 1;
        CP_WAIT0();
        __syncthreads();
        if (c + 1 < NCH) { load_stage(s ^ 1, c + 1); CP_COMMIT(); }

        const uint32_t st = sbase + s * STAGEB;
        #pragma unroll
        for (int ks = 0; ks < 2; ks++) {
            const uint32_t kb = (uint32_t)(ks * 32);
            uint32_t ah[4][4], al[4][4];
            uint32_t bh[4][2], bl[4][2];
            #pragma unroll
            for (int mt = 0; mt < 4; mt++) {
                uint32_t ra = st + (uint32_t)((wm * 64 + mt * 16) * ROWB) + kb + a_off;
                ldsm4(ah[mt], ra);
                ldsm4(al[mt], ra + TILEB);
            }
            #pragma unroll
            for (int np = 0; np < 2; np++) {
                uint32_t rb = st + 2 * TILEB +
                              (uint32_t)((wn * 32 + np * 16) * ROWB) + kb + b_off;
                uint32_t rh[4], rl[4];
                ldsm4(rh, rb);
                ldsm4(rl, rb + TILEB);
                bh[2 * np][0] = rh[0]; bh[2 * np][1] = rh[1];
                bh[2 * np + 1][0] = rh[2]; bh[2 * np + 1][1] = rh[3];
                bl[2 * np][0] = rl[0]; bl[2 * np][1] = rl[1];
                bl[2 * np + 1][0] = rl[2]; bl[2 * np + 1][1] = rl[3];
            }
            #pragma unroll
            for (int mt = 0; mt < 4; mt++)
                #pragma unroll
                for (int nt = 0; nt < 4; nt++) {
                    mma16816(acc[mt][nt], ah[mt], bh[nt][0], bh[nt][1]);
                    mma16816(acc[mt][nt], ah[mt], bl[nt][0], bl[nt][1]);
                    mma16816(acc[mt][nt], al[mt], bh[nt][0], bh[nt][1]);
                }
        }
    }
}

// Fused QKV GEMM: blockIdx.y in [0,18): wsel = y/6 (0=Q,1=K,2=V), col tile y%6.
// Writes bf16 hi/lo splits.
__global__ __launch_bounds__(256) void mma_gemm_qkv(
    const bf16* __restrict__ Xhi, const bf16* __restrict__ Xlo,
    const bf16* __restrict__ Whi, const bf16* __restrict__ Wlo,
    const float* __restrict__ bq, const float* __restrict__ bk,
    const float* __restrict__ bv,
    bf16* __restrict__ qhi, bf16* __restrict__ qlo,
    bf16* __restrict__ khi, bf16* __restrict__ klo,
    bf16* __restrict__ vhi, bf16* __restrict__ vlo)
{
    extern __shared__ char smem[];
    const uint32_t sbase = smem_u32(smem);

    const int wsel = blockIdx.y / 6;
    const int row0 = blockIdx.x * 128;
    const int col0 = (blockIdx.y % 6) * 128;
    const size_t WSZ = (size_t)EMBED * EMBED;

    const bf16* Bh = Whi + (size_t)wsel * WSZ;
    const bf16* Bl = Wlo + (size_t)wsel * WSZ;
    const float* bias = (wsel == 0) ? bq : (wsel == 1) ? bk : bv;
    bf16* Yhi = (wsel == 0) ? qhi : (wsel == 1) ? khi : vhi;
    bf16* Ylo = (wsel == 0) ? qlo : (wsel == 1) ? klo : vlo;
    const float scale = (wsel == 0) ? 0.125f : 1.f;

    float acc[4][4][4];
    #pragma unroll
    for (int mt = 0; mt < 4; mt++)
        #pragma unroll
        for (int nt = 0; nt < 4; nt++)
            #pragma unroll
            for (int u = 0; u < 4; u++) acc[mt][nt][u] = 0.f;

    gemm_mainloop(Xhi, Xlo, Bh, Bl, row0, col0, sbase, acc);

    const int lane = threadIdx.x & 31;
    const int wid  = threadIdx.x >> 5;
    const int wm   = wid >> 2;
    const int wn   = wid & 3;

    #pragma unroll
    for (int mt = 0; mt < 4; mt++) {
        int r0 = row0 + wm * 64 + mt * 16 + (lane >> 2);
        #pragma unroll
        for (int nt = 0; nt < 4; nt++) {
            int mcol = col0 + wn * 32 + nt * 8 + 2 * (lane & 3);
            float b0 = bias[mcol], b1 = bias[mcol + 1];
            float o0 = (acc[mt][nt][0] + b0) * scale;
            float o1 = (acc[mt][nt][1] + b1) * scale;
            float o2 = (acc[mt][nt][2] + b0) * scale;
            float o3 = (acc[mt][nt][3] + b1) * scale;
            bf16 h0 = __float2bfloat16(o0), h1 = __float2bfloat16(o1);
            bf16 h2 = __float2bfloat16(o2), h3 = __float2bfloat16(o3);
            *(bf162*)(Yhi + (size_t)r0 * EMBED + mcol) = bf162(h0, h1);
            *(bf162*)(Yhi + (size_t)(r0 + 8) * EMBED + mcol) = bf162(h2, h3);
            bf16 l0 = __float2bfloat16(o0 - __bfloat162float(h0));
            bf16 l1 = __float2bfloat16(o1 - __bfloat162float(h1));
            bf16 l2 = __float2bfloat16(o2 - __bfloat162float(h2));
            bf16 l3 = __float2bfloat16(o3 - __bfloat162float(h3));
            *(bf162*)(Ylo + (size_t)r0 * EMBED + mcol) = bf162(l0, l1);
            *(bf162*)(Ylo + (size_t)(r0 + 8) * EMBED + mcol) = bf162(l2, l3);
        }
    }
}

// Output-projection GEMM: f32 output.
__global__ __launch_bounds__(256) void mma_gemm_out(
    const bf16* __restrict__ Ahi, const bf16* __restrict__ Alo,
    const bf16* __restrict__ Bhi, const bf16* __restrict__ Blo,
    const float* __restrict__ bias, float* __restrict__ Yf)
{
    extern __shared__ char smem[];
    const uint32_t sbase = smem_u32(smem);
    const int row0 = blockIdx.x * 128;
    const int col0 = blockIdx.y * 128;

    float acc[4][4][4];
    #pragma unroll
    for (int mt = 0; mt < 4; mt++)
        #pragma unroll
        for (int nt = 0; nt < 4; nt++)
            #pragma unroll
            for (int u = 0; u < 4; u++) acc[mt][nt][u] = 0.f;

    gemm_mainloop(Ahi, Alo, Bhi, Blo, row0, col0, sbase, acc);

    const int lane = threadIdx.x & 31;
    const int wid  = threadIdx.x >> 5;
    const int wm   = wid >> 2;
    const int wn   = wid & 3;

    #pragma unroll
    for (int mt = 0; mt < 4; mt++) {
        int r0 = row0 + wm * 64 + mt * 16 + (lane >> 2);
        #pragma unroll
        for (int nt = 0; nt < 4; nt++) {
            int mcol = col0 + wn * 32 + nt * 8 + 2 * (lane & 3);
            float b0 = bias[mcol], b1 = bias[mcol + 1];
            *(float2*)(Yf + (size_t)r0 * EMBED + mcol) =
                make_float2(acc[mt][nt][0] + b0, acc[mt][nt][1] + b1);
            *(float2*)(Yf + (size_t)(r0 + 8) * EMBED + mcol) =
                make_float2(acc[mt][nt][2] + b0, acc[mt][nt][3] + b1);
        }
    }
}

// ---------------------------------------------------------------------------
// Attention via mma.sync. One block per (c, h); 8 warps; warp owns 16 i-rows.
// ---------------------------------------------------------------------------
#define AT_QHI 0
#define AT_QLO 16384
#define AT_KHI 32768
#define AT_KLO 49152
#define AT_VHI 65536
#define AT_VLO 81920
#define AT_PHI 98304
#define AT_PLO 131072
#define AT_MKW 163840
#define AT_SMEM (163840 + 32)

__device__ __forceinline__ uint32_t qswz(int r, int c) {
    return (uint32_t)(r * 128 + ((c ^ (r & 7)) * 16));
}
__device__ __forceinline__ uint32_t pswz(int r, int c) {
    return (uint32_t)(r * 256 + (((c & 8) | ((c & 7) ^ (r & 7))) * 16));
}

__global__ __launch_bounds__(256) void attn_mma(
    const bf16* __restrict__ qhi, const bf16* __restrict__ qlo,
    const bf16* __restrict__ khi, const bf16* __restrict__ klo,
    const bf16* __restrict__ vhi, const bf16* __restrict__ vlo,
    const unsigned char* __restrict__ mask, float* __restrict__ probs,
    bf16* __restrict__ chi, bf16* __restrict__ clo, int write_probs)
{
    extern __shared__ char smc[];
    const uint32_t sb = smem_u32(smc);

    const int c = blockIdx.x;
    const int h = blockIdx.y;
    const int tid = threadIdx.x;
    const int wid = tid >> 5;
    const int lane = tid & 31;
    const size_t base = (size_t)c * EMBED + h * DKK;

    {
        const bf16* srcs[6] = { qhi, qlo, khi, klo, vhi, vlo };
        #pragma unroll
        for (int t = 0; t < 6; t++) {
            #pragma unroll
            for (int it = 0; it < 4; it++) {
                int e = tid + it * 256;
                int r = e >> 3;
                int ch = e & 7;
                CP_ASYNC16(sb + (uint32_t)(t * 16384) + qswz(r, ch),
                           srcs[t] + (size_t)r * (CDIM * EMBED) + base + ch * 8);
            }
        }
        CP_COMMIT();
    }
    if (tid < 4) {
        uint32_t w = 0;
        for (int b = 0; b < 32; b++)
            if (mask[(size_t)(tid * 32 + b) * CDIM + c]) w |= (1u << b);
        *(uint32_t*)(smc + AT_MKW + tid * 4) = w;
    }
    CP_WAIT0();
    __syncthreads();

    const int i0 = wid * 16;

    float acc[16][4];
    #pragma unroll
    for (int nt = 0; nt < 16; nt++)
        #pragma unroll
        for (int u = 0; u < 4; u++) acc[nt][u] = 0.f;

    #pragma unroll
    for (int ks = 0; ks < 4; ks++) {
        uint32_t ah[4], al[4];
        {
            int rr = i0 + (lane & 15);
            int cc = 2 * ks + (lane >> 4);
            uint32_t ad = sb + AT_QHI + qswz(rr, cc);
            ldsm4(ah, ad);
            ldsm4(al, ad + 16384);
        }
        #pragma unroll
        for (int jg = 0; jg < 8; jg++) {
            int jr = jg * 16 + ((lane & 16) >> 1) + (lane & 7);
            int cc = 2 * ks + ((lane >> 3) & 1);
            uint32_t bd = sb + AT_KHI + qswz(jr, cc);
            uint32_t bh[4], bl[4];
            ldsm4(bh, bd);
            ldsm4(bl, bd + 16384);
            mma16816(acc[2 * jg], ah, bh[0], bh[1]);
            mma16816(acc[2 * jg], ah, bl[0], bl[1]);
            mma16816(acc[2 * jg], al, bh[0], bh[1]);
            mma16816(acc[2 * jg + 1], ah, bh[2], bh[3]);
            mma16816(acc[2 * jg + 1], ah, bl[2], bl[3]);
            mma16816(acc[2 * jg + 1], al, bh[2], bh[3]);
        }
    }

    {
        uint32_t mw[4];
        #pragma unroll
        for (int u = 0; u < 4; u++) mw[u] = *(const uint32_t*)(smc + AT_MKW + u * 4);
        const int jb = (lane & 3) * 2;

        float mxl = -1e30f, mxh = -1e30f;
        #pragma unroll
        for (int nt = 0; nt < 16; nt++) {
            int j0 = nt * 8 + jb;
            bool m0 = (mw[j0 >> 5] >> (j0 & 31)) & 1;
            bool m1 = (mw[j0 >> 5] >> ((j0 + 1) & 31)) & 1;
            if (m0) { acc[nt][0] = -10000.f; acc[nt][2] = -10000.f; }
            if (m1) { acc[nt][1] = -10000.f; acc[nt][3] = -10000.f; }
            mxl = fmaxf(mxl, fmaxf(acc[nt][0], acc[nt][1]));
            mxh = fmaxf(mxh, fmaxf(acc[nt][2], acc[nt][3]));
        }
        #pragma unroll
        for (int o = 1; o <= 2; o <<= 1) {
            mxl = fmaxf(mxl, __shfl_xor_sync(0xffffffffu, mxl, o));
            mxh = fmaxf(mxh, __shfl_xor_sync(0xffffffffu, mxh, o));
        }
        float sl = 0.f, sh = 0.f;
        #pragma unroll
        for (int nt = 0; nt < 16; nt++) {
            acc[nt][0] = __expf(acc[nt][0] - mxl);
            acc[nt][1] = __expf(acc[nt][1] - mxl);
            acc[nt][2] = __expf(acc[nt][2] - mxh);
            acc[nt][3] = __expf(acc[nt][3] - mxh);
            sl += acc[nt][0] + acc[nt][1];
            sh += acc[nt][2] + acc[nt][3];
        }
        #pragma unroll
        for (int o = 1; o <= 2; o <<= 1) {
            sl += __shfl_xor_sync(0xffffffffu, sl, o);
            sh += __shfl_xor_sync(0xffffffffu, sh, o);
        }
        float il = 1.f / sl, ih = 1.f / sh;

        const int rl = i0 + (lane >> 2);
        #pragma unroll
        for (int nt = 0; nt < 16; nt++) {
            float p0 = acc[nt][0] * il;
            float p1 = acc[nt][1] * il;
            float p2 = acc[nt][2] * ih;
            float p3 = acc[nt][3] * ih;
            bf16 h0 = __float2bfloat16(p0), h1 = __float2bfloat16(p1);
            bf16 h2 = __float2bfloat16(p2), h3 = __float2bfloat16(p3);
            uint32_t a0 = pswz(rl, nt) + (uint32_t)(jb * 2);
            uint32_t a1 = pswz(rl + 8, nt) + (uint32_t)(jb * 2);
            *(bf162*)(smc + AT_PHI + a0) = bf162(h0, h1);
            *(bf162*)(smc + AT_PHI + a1) = bf162(h2, h3);
            bf16 l0 = __float2bfloat16(p0 - __bfloat162float(h0));
            bf16 l1 = __float2bfloat16(p1 - __bfloat162float(h1));
            bf16 l2 = __float2bfloat16(p2 - __bfloat162float(h2));
            bf16 l3 = __float2bfloat16(p3 - __bfloat162float(h3));
            *(bf162*)(smc + AT_PLO + a0) = bf162(l0, l1);
            *(bf162*)(smc + AT_PLO + a1) = bf162(l2, l3);
        }
    }
    __syncthreads();

    if (write_probs) {
        const size_t pb = ((size_t)(h * CDIM + c) * RDIM) * RDIM;
        #pragma unroll
        for (int it = 0; it < 16; it++) {
            int e = tid + it * 256;
            int r = e >> 5;
            int s2 = e & 31;
            uint32_t pa = pswz(r, s2 >> 1) + (uint32_t)((s2 & 1) * 8);
            uint2 uh = *(const uint2*)(smc + AT_PHI + pa);
            uint2 ul = *(const uint2*)(smc + AT_PLO + pa);
            bf162 h0 = *(bf162*)&uh.x, h1 = *(bf162*)&uh.y;
            bf162 l0 = *(bf162*)&ul.x, l1 = *(bf162*)&ul.y;
            float4 o;
            o.x = __bfloat162float(h0.x) + __bfloat162float(l0.x);
            o.y = __bfloat162float(h0.y) + __bfloat162float(l0.y);
            o.z = __bfloat162float(h1.x) + __bfloat162float(l1.x);
            o.w = __bfloat162float(h1.y) + __bfloat162float(l1.y);
            *(float4*)(probs + pb + (size_t)r * RDIM + s2 * 4) = o;
        }
    }

    float acc2[8][4];
    #pragma unroll
    for (int nt = 0; nt < 8; nt++)
        #pragma unroll
        for (int u = 0; u < 4; u++) acc2[nt][u] = 0.f;

    #pragma unroll
    for (int j16 = 0; j16 < 8; j16++) {
        uint32_t ph4[4], pl4[4];
        {
            int rr = i0 + (lane & 15);
            int cc = 2 * j16 + (lane >> 4);
            uint32_t ad = sb + AT_PHI + pswz(rr, cc);
            ldsm4(ph4, ad);
            ldsm4(pl4, ad + 32768);
        }
        #pragma unroll
        for (int dg = 0; dg < 4; dg++) {
            int jr = j16 * 16 + (lane & 7) + ((lane >> 3) & 1) * 8;
            int cc = 2 * dg + (lane >> 4);
            uint32_t vd = sb + AT_VHI + qswz(jr, cc);
            uint32_t vh4[4], vl4[4];
            ldsm4t(vh4, vd);
            ldsm4t(vl4, vd + 16384);
            mma16816(acc2[2 * dg], ph4, vh4[0], vh4[1]);
            mma16816(acc2[2 * dg], ph4, vl4[0], vl4[1]);
            mma16816(acc2[2 * dg], pl4, vh4[0], vh4[1]);
            mma16816(acc2[2 * dg + 1], ph4, vh4[2], vh4[3]);
            mma16816(acc2[2 * dg + 1], ph4, vl4[2], vl4[3]);
            mma16816(acc2[2 * dg + 1], pl4, vh4[2], vh4[3]);
        }
    }

    {
        const int r0 = i0 + (lane >> 2);
        #pragma unroll
        for (int nt = 0; nt < 8; nt++) {
            int d0 = nt * 8 + (lane & 3) * 2;
            float o0 = acc2[nt][0], o1 = acc2[nt][1];
            float o2 = acc2[nt][2], o3 = acc2[nt][3];
            bf16 h0 = __float2bfloat16(o0), h1 = __float2bfloat16(o1);
            bf16 h2 = __float2bfloat16(o2), h3 = __float2bfloat16(o3);
            size_t g0 = (size_t)r0 * (CDIM * EMBED) + base + d0;
            size_t g1 = (size_t)(r0 + 8) * (CDIM * EMBED) + base + d0;
            *(bf162*)(chi + g0) = bf162(h0, h1);
            *(bf162*)(chi + g1) = bf162(h2, h3);
            bf16 l0 = __float2bfloat16(o0 - __bfloat162float(h0));
            bf16 l1 = __float2bfloat16(o1 - __bfloat162float(h1));
            bf16 l2 = __float2bfloat16(o2 - __bfloat162float(h2));
            bf16 l3 = __float2bfloat16(o3 - __bfloat162float(h3));
            *(bf162*)(clo + g0) = bf162(l0, l1);
            *(bf162*)(clo + g1) = bf162(l2, l3);
        }
    }
}

// ---------------------------------------------------------------------------
extern "C" void kernel_launch(void* const* d_in, const int* in_sizes, int n_in,
                              void* d_out, int out_size)
{
    const float* x  = (const float*)d_in[0];
    const unsigned char* mask = (const unsigned char*)d_in[1];
    const float* Wq = (const float*)d_in[2];
    const float* bq = (const float*)d_in[3];
    const float* Wk = (const float*)d_in[4];
    const float* bk = (const float*)d_in[5];
    const float* Wv = (const float*)d_in[6];
    const float* bv = (const float*)d_in[7];
    const float* Wo = (const float*)d_in[8];
    const float* bo = (const float*)d_in[9];
    float* out = (float*)d_out;

    bf16 *xhi, *xlo, *qhi, *qlo, *khi, *klo, *vhi, *vlo, *whi, *wlo;
    cudaGetSymbolAddress((void**)&xhi, g_xhi);
    cudaGetSymbolAddress((void**)&xlo, g_xlo);
    cudaGetSymbolAddress((void**)&qhi, g_qhi);
    cudaGetSymbolAddress((void**)&qlo, g_qlo);
    cudaGetSymbolAddress((void**)&khi, g_khi);
    cudaGetSymbolAddress((void**)&klo, g_klo);
    cudaGetSymbolAddress((void**)&vhi, g_vhi);
    cudaGetSymbolAddress((void**)&vlo, g_vlo);
    cudaGetSymbolAddress((void**)&whi, g_whi);
    cudaGetSymbolAddress((void**)&wlo, g_wlo);

    const long long out_elems = (long long)NTOK * EMBED;
    const long long probs_elems = (long long)HEADS * CDIM * RDIM * RDIM;
    int write_probs = ((long long)out_size >= out_elems + probs_elems) ? 1 : 0;
    float* probs = write_probs ? (out + out_elems) : nullptr;

    const int gemm_smem = 2 * STAGEB;   // 81920
    cudaFuncSetAttribute(mma_gemm_qkv, cudaFuncAttributeMaxDynamicSharedMemorySize, gemm_smem);
    cudaFuncSetAttribute(mma_gemm_out, cudaFuncAttributeMaxDynamicSharedMemorySize, gemm_smem);
    cudaFuncSetAttribute(attn_mma, cudaFuncAttributeMaxDynamicSharedMemorySize, AT_SMEM);

    const size_t WSZ = (size_t)EMBED * EMBED;
    const int xn4 = (int)(((size_t)NTOK * EMBED) / 4);
    const int wn4 = (int)(WSZ / 4);

    split_kernel<<<(xn4 + 255) / 256, 256>>>((const float4*)x, xhi, xlo, xn4);
    {
        dim3 wgrid((wn4 + 255) / 256, 4);
        split_w_kernel<<<wgrid, 256>>>((const float4*)Wq, (const float4*)Wk,
                                       (const float4*)Wv, (const float4*)Wo,
                                       whi, wlo, wn4);
    }

    dim3 qkvgrid(NTOK / 128, 18);
    mma_gemm_qkv<<<qkvgrid, 256, gemm_smem>>>(xhi, xlo, whi, wlo,
                                              bq, bk, bv,
                                              qhi, qlo, khi, klo, vhi, vlo);

    dim3 agrid(CDIM, HEADS);
    attn_mma<<<agrid, 256, AT_SMEM>>>(qhi, qlo, khi, klo, vhi, vlo,
                                      mask, probs, xhi, xlo, write_probs);

    dim3 ogrid(NTOK / 128, EMBED / 128);
    mma_gemm_out<<<ogrid, 256, gemm_smem>>>(xhi, xlo, whi + 3 * WSZ, wlo + 3 * WSZ,
                                            bo, out);
}

// round 8
// speedup vs baseline: 3.3490x; 1.0287x over previous
#include <cuda_runtime.h>
#include <cuda_bf16.h>
#include <cstdint>

#define EMBED 768
#define HEADS 12
#define DKK   64
#define RDIM  128
#define CDIM  256
#define NTOK  (RDIM * CDIM)   // 32768

typedef __nv_bfloat16 bf16;
typedef __nv_bfloat162 bf162;

// ---------------------------------------------------------------------------
// Scratch (allocation-free rule: __device__ globals).
// x splits double as context splits after the QKV GEMMs consume them.
// ---------------------------------------------------------------------------
__device__ bf16 g_xhi[(size_t)NTOK * EMBED];
__device__ bf16 g_xlo[(size_t)NTOK * EMBED];
__device__ bf16 g_qhi[(size_t)NTOK * EMBED];
__device__ bf16 g_qlo[(size_t)NTOK * EMBED];
__device__ bf16 g_khi[(size_t)NTOK * EMBED];
__device__ bf16 g_klo[(size_t)NTOK * EMBED];
__device__ bf16 g_vhi[(size_t)NTOK * EMBED];
__device__ bf16 g_vlo[(size_t)NTOK * EMBED];
__device__ bf16 g_whi[4 * (size_t)EMBED * EMBED];
__device__ bf16 g_wlo[4 * (size_t)EMBED * EMBED];

__device__ __forceinline__ uint32_t smem_u32(const void* p) {
    uint32_t a;
    asm("{ .reg .u64 t; cvta.to.shared.u64 t, %1; cvt.u32.u64 %0, t; }"
        : "=r"(a) : "l"(p));
    return a;
}

__device__ __forceinline__ void ldsm4(uint32_t (&r)[4], uint32_t addr) {
    asm volatile("ldmatrix.sync.aligned.m8n8.x4.shared.b16 {%0,%1,%2,%3}, [%4];"
                 : "=r"(r[0]), "=r"(r[1]), "=r"(r[2]), "=r"(r[3]) : "r"(addr));
}

__device__ __forceinline__ void ldsm4t(uint32_t (&r)[4], uint32_t addr) {
    asm volatile("ldmatrix.sync.aligned.m8n8.x4.trans.shared.b16 {%0,%1,%2,%3}, [%4];"
                 : "=r"(r[0]), "=r"(r[1]), "=r"(r[2]), "=r"(r[3]) : "r"(addr));
}

__device__ __forceinline__ void mma16816(float (&c)[4], const uint32_t (&a)[4],
                                         uint32_t b0, uint32_t b1) {
    asm volatile(
        "mma.sync.aligned.m16n8k16.row.col.f32.bf16.bf16.f32 "
        "{%0,%1,%2,%3}, {%4,%5,%6,%7}, {%8,%9}, {%0,%1,%2,%3};"
        : "+f"(c[0]), "+f"(c[1]), "+f"(c[2]), "+f"(c[3])
        : "r"(a[0]), "r"(a[1]), "r"(a[2]), "r"(a[3]), "r"(b0), "r"(b1));
}

#define CP_ASYNC16(dst, src) \
    asm volatile("cp.async.cg.shared.global [%0], [%1], 16;" \
                 :: "r"(dst), "l"(src))
#define CP_COMMIT() asm volatile("cp.async.commit_group;" ::: "memory")
#define CP_WAIT0()  asm volatile("cp.async.wait_group 0;" ::: "memory")

// ---------------------------------------------------------------------------
// split fp32 -> (hi bf16, lo bf16)
// ---------------------------------------------------------------------------
__device__ __forceinline__ void split4(const float4 v, bf162* hp, bf162* lp) {
    bf16 h0 = __float2bfloat16(v.x);
    bf16 h1 = __float2bfloat16(v.y);
    bf16 h2 = __float2bfloat16(v.z);
    bf16 h3 = __float2bfloat16(v.w);
    bf16 l0 = __float2bfloat16(v.x - __bfloat162float(h0));
    bf16 l1 = __float2bfloat16(v.y - __bfloat162float(h1));
    bf16 l2 = __float2bfloat16(v.z - __bfloat162float(h2));
    bf16 l3 = __float2bfloat16(v.w - __bfloat162float(h3));
    hp[0] = bf162(h0, h1);
    hp[1] = bf162(h2, h3);
    lp[0] = bf162(l0, l1);
    lp[1] = bf162(l2, l3);
}

__global__ __launch_bounds__(256) void split_kernel(
    const float4* __restrict__ src, bf16* __restrict__ hi,
    bf16* __restrict__ lo, int n4)
{
    int i = blockIdx.x * blockDim.x + threadIdx.x;
    if (i >= n4) return;
    split4(src[i], (bf162*)(hi + (size_t)i * 4), (bf162*)(lo + (size_t)i * 4));
}

// one launch for all 4 weight matrices; blockIdx.y selects the weight
__global__ __launch_bounds__(256) void split_w_kernel(
    const float4* __restrict__ w0, const float4* __restrict__ w1,
    const float4* __restrict__ w2, const float4* __restrict__ w3,
    bf16* __restrict__ hi, bf16* __restrict__ lo, int n4)
{
    int i = blockIdx.x * blockDim.x + threadIdx.x;
    if (i >= n4) return;
    const float4* src = (blockIdx.y == 0) ? w0 : (blockIdx.y == 1) ? w1 :
                        (blockIdx.y == 2) ? w2 : w3;
    size_t o = (size_t)blockIdx.y * n4 * 4 + (size_t)i * 4;
    split4(src[i], (bf162*)(hi + o), (bf162*)(lo + o));
}

// ---------------------------------------------------------------------------
// mma.sync split-bf16 GEMM mainloop (shared by both GEMM kernels).
// CTA 128x128, 8 warps, K-chunk 32, cp.async double-buffered smem.
// ---------------------------------------------------------------------------
#define KC      32
#define NCH     (EMBED / KC)          // 24
#define ROWB    80
#define TILEB   (128 * ROWB)          // 10240 B
#define STAGEB  (4 * TILEB)

__device__ __forceinline__ void gemm_mainloop(
    const bf16* __restrict__ Ahi, const bf16* __restrict__ Alo,
    const bf16* __restrict__ Bhi, const bf16* __restrict__ Blo,
    int row0, int col0, uint32_t sbase, float (&acc)[4][4][4])
{
    const int tid  = threadIdx.x;
    const int wid  = tid >> 5;
    const int lane = tid & 31;
    const int wm   = wid >> 2;
    const int wn   = wid & 3;

    const uint32_t a_off = (uint32_t)((lane & 15) * ROWB + (lane >> 4) * 16);
    const uint32_t b_off = (uint32_t)((((lane & 16) >> 1) + (lane & 7)) * ROWB +
                                      (((lane >> 3) & 1) * 16));

    auto load_stage = [&](int s, int c) {
        uint32_t stage = sbase + s * STAGEB;
        #pragma unroll
        for (int it = 0; it < 8; it++) {
            int u = tid + it * 256;
            int t = u >> 9;
            int rem = u & 511;
            int r = rem >> 2;
            int g = rem & 3;
            const bf16* src;
            int grow;
            if (t == 0)      { src = Ahi; grow = row0 + r; }
            else if (t == 1) { src = Alo; grow = row0 + r; }
            else if (t == 2) { src = Bhi; grow = col0 + r; }
            else             { src = Blo; grow = col0 + r; }
            CP_ASYNC16(stage + (uint32_t)(t * TILEB + r * ROWB + g * 16),
                       src + (size_t)grow * EMBED + c * KC + g * 8);
        }
    };

    load_stage(0, 0);
    CP_COMMIT();

    for (int c = 0; c < NCH; c++) {
        const int s = c & 1;
        CP_WAIT0();
        __syncthreads();
        if (c + 1 < NCH) { load_stage(s ^ 1, c + 1); CP_COMMIT(); }

        const uint32_t st = sbase + s * STAGEB;
        #pragma unroll
        for (int ks = 0; ks < 2; ks++) {
            const uint32_t kb = (uint32_t)(ks * 32);
            uint32_t ah[4][4], al[4][4];
            uint32_t bh[4][2], bl[4][2];
            #pragma unroll
            for (int mt = 0; mt < 4; mt++) {
                uint32_t ra = st + (uint32_t)((wm * 64 + mt * 16) * ROWB) + kb + a_off;
                ldsm4(ah[mt], ra);
                ldsm4(al[mt], ra + TILEB);
            }
            #pragma unroll
            for (int np = 0; np < 2; np++) {
                uint32_t rb = st + 2 * TILEB +
                              (uint32_t)((wn * 32 + np * 16) * ROWB) + kb + b_off;
                uint32_t rh[4], rl[4];
                ldsm4(rh, rb);
                ldsm4(rl, rb + TILEB);
                bh[2 * np][0] = rh[0]; bh[2 * np][1] = rh[1];
                bh[2 * np + 1][0] = rh[2]; bh[2 * np + 1][1] = rh[3];
                bl[2 * np][0] = rl[0]; bl[2 * np][1] = rl[1];
                bl[2 * np + 1][0] = rl[2]; bl[2 * np + 1][1] = rl[3];
            }
            #pragma unroll
            for (int mt = 0; mt < 4; mt++)
                #pragma unroll
                for (int nt = 0; nt < 4; nt++) {
                    mma16816(acc[mt][nt], ah[mt], bh[nt][0], bh[nt][1]);
                    mma16816(acc[mt][nt], ah[mt], bl[nt][0], bl[nt][1]);
                    mma16816(acc[mt][nt], al[mt], bh[nt][0], bh[nt][1]);
                }
        }
    }
}

// Fused QKV GEMM: blockIdx.y in [0,18): wsel = y/6 (0=Q,1=K,2=V), col tile y%6.
// Writes bf16 hi/lo splits.
__global__ __launch_bounds__(256) void mma_gemm_qkv(
    const bf16* __restrict__ Xhi, const bf16* __restrict__ Xlo,
    const bf16* __restrict__ Whi, const bf16* __restrict__ Wlo,
    const float* __restrict__ bq, const float* __restrict__ bk,
    const float* __restrict__ bv,
    bf16* __restrict__ qhi, bf16* __restrict__ qlo,
    bf16* __restrict__ khi, bf16* __restrict__ klo,
    bf16* __restrict__ vhi, bf16* __restrict__ vlo)
{
    extern __shared__ char smem[];
    const uint32_t sbase = smem_u32(smem);

    const int wsel = blockIdx.y / 6;
    const int row0 = blockIdx.x * 128;
    const int col0 = (blockIdx.y % 6) * 128;
    const size_t WSZ = (size_t)EMBED * EMBED;

    const bf16* Bh = Whi + (size_t)wsel * WSZ;
    const bf16* Bl = Wlo + (size_t)wsel * WSZ;
    const float* bias = (wsel == 0) ? bq : (wsel == 1) ? bk : bv;
    bf16* Yhi = (wsel == 0) ? qhi : (wsel == 1) ? khi : vhi;
    bf16* Ylo = (wsel == 0) ? qlo : (wsel == 1) ? klo : vlo;
    const float scale = (wsel == 0) ? 0.125f : 1.f;

    float acc[4][4][4];
    #pragma unroll
    for (int mt = 0; mt < 4; mt++)
        #pragma unroll
        for (int nt = 0; nt < 4; nt++)
            #pragma unroll
            for (int u = 0; u < 4; u++) acc[mt][nt][u] = 0.f;

    gemm_mainloop(Xhi, Xlo, Bh, Bl, row0, col0, sbase, acc);

    const int lane = threadIdx.x & 31;
    const int wid  = threadIdx.x >> 5;
    const int wm   = wid >> 2;
    const int wn   = wid & 3;

    #pragma unroll
    for (int mt = 0; mt < 4; mt++) {
        int r0 = row0 + wm * 64 + mt * 16 + (lane >> 2);
        #pragma unroll
        for (int nt = 0; nt < 4; nt++) {
            int mcol = col0 + wn * 32 + nt * 8 + 2 * (lane & 3);
            float b0 = bias[mcol], b1 = bias[mcol + 1];
            float o0 = (acc[mt][nt][0] + b0) * scale;
            float o1 = (acc[mt][nt][1] + b1) * scale;
            float o2 = (acc[mt][nt][2] + b0) * scale;
            float o3 = (acc[mt][nt][3] + b1) * scale;
            bf16 h0 = __float2bfloat16(o0), h1 = __float2bfloat16(o1);
            bf16 h2 = __float2bfloat16(o2), h3 = __float2bfloat16(o3);
            *(bf162*)(Yhi + (size_t)r0 * EMBED + mcol) = bf162(h0, h1);
            *(bf162*)(Yhi + (size_t)(r0 + 8) * EMBED + mcol) = bf162(h2, h3);
            bf16 l0 = __float2bfloat16(o0 - __bfloat162float(h0));
            bf16 l1 = __float2bfloat16(o1 - __bfloat162float(h1));
            bf16 l2 = __float2bfloat16(o2 - __bfloat162float(h2));
            bf16 l3 = __float2bfloat16(o3 - __bfloat162float(h3));
            *(bf162*)(Ylo + (size_t)r0 * EMBED + mcol) = bf162(l0, l1);
            *(bf162*)(Ylo + (size_t)(r0 + 8) * EMBED + mcol) = bf162(l2, l3);
        }
    }
}

// Output-projection GEMM: f32 output.
__global__ __launch_bounds__(256) void mma_gemm_out(
    const bf16* __restrict__ Ahi, const bf16* __restrict__ Alo,
    const bf16* __restrict__ Bhi, const bf16* __restrict__ Blo,
    const float* __restrict__ bias, float* __restrict__ Yf)
{
    extern __shared__ char smem[];
    const uint32_t sbase = smem_u32(smem);
    const int row0 = blockIdx.x * 128;
    const int col0 = blockIdx.y * 128;

    float acc[4][4][4];
    #pragma unroll
    for (int mt = 0; mt < 4; mt++)
        #pragma unroll
        for (int nt = 0; nt < 4; nt++)
            #pragma unroll
            for (int u = 0; u < 4; u++) acc[mt][nt][u] = 0.f;

    gemm_mainloop(Ahi, Alo, Bhi, Blo, row0, col0, sbase, acc);

    const int lane = threadIdx.x & 31;
    const int wid  = threadIdx.x >> 5;
    const int wm   = wid >> 2;
    const int wn   = wid & 3;

    #pragma unroll
    for (int mt = 0; mt < 4; mt++) {
        int r0 = row0 + wm * 64 + mt * 16 + (lane >> 2);
        #pragma unroll
        for (int nt = 0; nt < 4; nt++) {
            int mcol = col0 + wn * 32 + nt * 8 + 2 * (lane & 3);
            float b0 = bias[mcol], b1 = bias[mcol + 1];
            *(float2*)(Yf + (size_t)r0 * EMBED + mcol) =
                make_float2(acc[mt][nt][0] + b0, acc[mt][nt][1] + b1);
            *(float2*)(Yf + (size_t)(r0 + 8) * EMBED + mcol) =
                make_float2(acc[mt][nt][2] + b0, acc[mt][nt][3] + b1);
        }
    }
}

// ---------------------------------------------------------------------------
// Attention via mma.sync. One block per (c, h); 8 warps; warp owns 16 i-rows.
// smem 96KB (2 CTAs/SM): P tiles OVERLAY the dead Q/K tiles after QK^T.
//   Qhi 0, Qlo 16K, Khi 32K, Klo 48K, Vhi 64K, Vlo 80K
//   Phi overlays 0..32K (Q), Plo overlays 32..64K (K), mask @96K
// ---------------------------------------------------------------------------
#define AT_QHI 0
#define AT_QLO 16384
#define AT_KHI 32768
#define AT_KLO 49152
#define AT_VHI 65536
#define AT_VLO 81920
#define AT_PHI 0
#define AT_PLO 32768
#define AT_MKW 98304
#define AT_SMEM (98304 + 32)

__device__ __forceinline__ uint32_t qswz(int r, int c) {
    return (uint32_t)(r * 128 + ((c ^ (r & 7)) * 16));
}
__device__ __forceinline__ uint32_t pswz(int r, int c) {
    return (uint32_t)(r * 256 + (((c & 8) | ((c & 7) ^ (r & 7))) * 16));
}

__global__ __launch_bounds__(256) void attn_mma(
    const bf16* __restrict__ qhi, const bf16* __restrict__ qlo,
    const bf16* __restrict__ khi, const bf16* __restrict__ klo,
    const bf16* __restrict__ vhi, const bf16* __restrict__ vlo,
    const unsigned char* __restrict__ mask, float* __restrict__ probs,
    bf16* __restrict__ chi, bf16* __restrict__ clo, int write_probs)
{
    extern __shared__ char smc[];
    const uint32_t sb = smem_u32(smc);

    const int c = blockIdx.x;
    const int h = blockIdx.y;
    const int tid = threadIdx.x;
    const int wid = tid >> 5;
    const int lane = tid & 31;
    const size_t base = (size_t)c * EMBED + h * DKK;

    {
        const bf16* srcs[6] = { qhi, qlo, khi, klo, vhi, vlo };
        #pragma unroll
        for (int t = 0; t < 6; t++) {
            #pragma unroll
            for (int it = 0; it < 4; it++) {
                int e = tid + it * 256;
                int r = e >> 3;
                int ch = e & 7;
                CP_ASYNC16(sb + (uint32_t)(t * 16384) + qswz(r, ch),
                           srcs[t] + (size_t)r * (CDIM * EMBED) + base + ch * 8);
            }
        }
        CP_COMMIT();
    }
    if (tid < 4) {
        uint32_t w = 0;
        for (int b = 0; b < 32; b++)
            if (mask[(size_t)(tid * 32 + b) * CDIM + c]) w |= (1u << b);
        *(uint32_t*)(smc + AT_MKW + tid * 4) = w;
    }
    CP_WAIT0();
    __syncthreads();

    const int i0 = wid * 16;

    float acc[16][4];
    #pragma unroll
    for (int nt = 0; nt < 16; nt++)
        #pragma unroll
        for (int u = 0; u < 4; u++) acc[nt][u] = 0.f;

    #pragma unroll
    for (int ks = 0; ks < 4; ks++) {
        uint32_t ah[4], al[4];
        {
            int rr = i0 + (lane & 15);
            int cc = 2 * ks + (lane >> 4);
            uint32_t ad = sb + AT_QHI + qswz(rr, cc);
            ldsm4(ah, ad);
            ldsm4(al, ad + 16384);
        }
        #pragma unroll
        for (int jg = 0; jg < 8; jg++) {
            int jr = jg * 16 + ((lane & 16) >> 1) + (lane & 7);
            int cc = 2 * ks + ((lane >> 3) & 1);
            uint32_t bd = sb + AT_KHI + qswz(jr, cc);
            uint32_t bh[4], bl[4];
            ldsm4(bh, bd);
            ldsm4(bl, bd + 16384);
            mma16816(acc[2 * jg], ah, bh[0], bh[1]);
            mma16816(acc[2 * jg], ah, bl[0], bl[1]);
            mma16816(acc[2 * jg], al, bh[0], bh[1]);
            mma16816(acc[2 * jg + 1], ah, bh[2], bh[3]);
            mma16816(acc[2 * jg + 1], ah, bl[2], bl[3]);
            mma16816(acc[2 * jg + 1], al, bh[2], bh[3]);
        }
    }

    // All warps must finish reading Q/K before P overlays them.
    __syncthreads();

    {
        uint32_t mw[4];
        #pragma unroll
        for (int u = 0; u < 4; u++) mw[u] = *(const uint32_t*)(smc + AT_MKW + u * 4);
        const int jb = (lane & 3) * 2;

        float mxl = -1e30f, mxh = -1e30f;
        #pragma unroll
        for (int nt = 0; nt < 16; nt++) {
            int j0 = nt * 8 + jb;
            bool m0 = (mw[j0 >> 5] >> (j0 & 31)) & 1;
            bool m1 = (mw[j0 >> 5] >> ((j0 + 1) & 31)) & 1;
            if (m0) { acc[nt][0] = -10000.f; acc[nt][2] = -10000.f; }
            if (m1) { acc[nt][1] = -10000.f; acc[nt][3] = -10000.f; }
            mxl = fmaxf(mxl, fmaxf(acc[nt][0], acc[nt][1]));
            mxh = fmaxf(mxh, fmaxf(acc[nt][2], acc[nt][3]));
        }
        #pragma unroll
        for (int o = 1; o <= 2; o <<= 1) {
            mxl = fmaxf(mxl, __shfl_xor_sync(0xffffffffu, mxl, o));
            mxh = fmaxf(mxh, __shfl_xor_sync(0xffffffffu, mxh, o));
        }
        float sl = 0.f, sh = 0.f;
        #pragma unroll
        for (int nt = 0; nt < 16; nt++) {
            acc[nt][0] = __expf(acc[nt][0] - mxl);
            acc[nt][1] = __expf(acc[nt][1] - mxl);
            acc[nt][2] = __expf(acc[nt][2] - mxh);
            acc[nt][3] = __expf(acc[nt][3] - mxh);
            sl += acc[nt][0] + acc[nt][1];
            sh += acc[nt][2] + acc[nt][3];
        }
        #pragma unroll
        for (int o = 1; o <= 2; o <<= 1) {
            sl += __shfl_xor_sync(0xffffffffu, sl, o);
            sh += __shfl_xor_sync(0xffffffffu, sh, o);
        }
        float il = 1.f / sl, ih = 1.f / sh;

        const int rl = i0 + (lane >> 2);
        #pragma unroll
        for (int nt = 0; nt < 16; nt++) {
            float p0 = acc[nt][0] * il;
            float p1 = acc[nt][1] * il;
            float p2 = acc[nt][2] * ih;
            float p3 = acc[nt][3] * ih;
            bf16 h0 = __float2bfloat16(p0), h1 = __float2bfloat16(p1);
            bf16 h2 = __float2bfloat16(p2), h3 = __float2bfloat16(p3);
            uint32_t a0 = pswz(rl, nt) + (uint32_t)(jb * 2);
            uint32_t a1 = pswz(rl + 8, nt) + (uint32_t)(jb * 2);
            *(bf162*)(smc + AT_PHI + a0) = bf162(h0, h1);
            *(bf162*)(smc + AT_PHI + a1) = bf162(h2, h3);
            bf16 l0 = __float2bfloat16(p0 - __bfloat162float(h0));
            bf16 l1 = __float2bfloat16(p1 - __bfloat162float(h1));
            bf16 l2 = __float2bfloat16(p2 - __bfloat162float(h2));
            bf16 l3 = __float2bfloat16(p3 - __bfloat162float(h3));
            *(bf162*)(smc + AT_PLO + a0) = bf162(l0, l1);
            *(bf162*)(smc + AT_PLO + a1) = bf162(l2, l3);
        }
    }
    __syncthreads();

    if (write_probs) {
        const size_t pb = ((size_t)(h * CDIM + c) * RDIM) * RDIM;
        #pragma unroll
        for (int it = 0; it < 16; it++) {
            int e = tid + it * 256;
            int r = e >> 5;
            int s2 = e & 31;
            uint32_t pa = pswz(r, s2 >> 1) + (uint32_t)((s2 & 1) * 8);
            uint2 uh = *(const uint2*)(smc + AT_PHI + pa);
            uint2 ul = *(const uint2*)(smc + AT_PLO + pa);
            bf162 h0 = *(bf162*)&uh.x, h1 = *(bf162*)&uh.y;
            bf162 l0 = *(bf162*)&ul.x, l1 = *(bf162*)&ul.y;
            float4 o;
            o.x = __bfloat162float(h0.x) + __bfloat162float(l0.x);
            o.y = __bfloat162float(h0.y) + __bfloat162float(l0.y);
            o.z = __bfloat162float(h1.x) + __bfloat162float(l1.x);
            o.w = __bfloat162float(h1.y) + __bfloat162float(l1.y);
            *(float4*)(probs + pb + (size_t)r * RDIM + s2 * 4) = o;
        }
    }

    float acc2[8][4];
    #pragma unroll
    for (int nt = 0; nt < 8; nt++)
        #pragma unroll
        for (int u = 0; u < 4; u++) acc2[nt][u] = 0.f;

    #pragma unroll
    for (int j16 = 0; j16 < 8; j16++) {
        uint32_t ph4[4], pl4[4];
        {
            int rr = i0 + (lane & 15);
            int cc = 2 * j16 + (lane >> 4);
            uint32_t ad = sb + AT_PHI + pswz(rr, cc);
            ldsm4(ph4, ad);
            ldsm4(pl4, ad + 32768);
        }
        #pragma unroll
        for (int dg = 0; dg < 4; dg++) {
            int jr = j16 * 16 + (lane & 7) + ((lane >> 3) & 1) * 8;
            int cc = 2 * dg + (lane >> 4);
            uint32_t vd = sb + AT_VHI + qswz(jr, cc);
            uint32_t vh4[4], vl4[4];
            ldsm4t(vh4, vd);
            ldsm4t(vl4, vd + 16384);
            mma16816(acc2[2 * dg], ph4, vh4[0], vh4[1]);
            mma16816(acc2[2 * dg], ph4, vl4[0], vl4[1]);
            mma16816(acc2[2 * dg], pl4, vh4[0], vh4[1]);
            mma16816(acc2[2 * dg + 1], ph4, vh4[2], vh4[3]);
            mma16816(acc2[2 * dg + 1], ph4, vl4[2], vl4[3]);
            mma16816(acc2[2 * dg + 1], pl4, vh4[2], vh4[3]);
        }
    }

    {
        const int r0 = i0 + (lane >> 2);
        #pragma unroll
        for (int nt = 0; nt < 8; nt++) {
            int d0 = nt * 8 + (lane & 3) * 2;
            float o0 = acc2[nt][0], o1 = acc2[nt][1];
            float o2 = acc2[nt][2], o3 = acc2[nt][3];
            bf16 h0 = __float2bfloat16(o0), h1 = __float2bfloat16(o1);
            bf16 h2 = __float2bfloat16(o2), h3 = __float2bfloat16(o3);
            size_t g0 = (size_t)r0 * (CDIM * EMBED) + base + d0;
            size_t g1 = (size_t)(r0 + 8) * (CDIM * EMBED) + base + d0;
            *(bf162*)(chi + g0) = bf162(h0, h1);
            *(bf162*)(chi + g1) = bf162(h2, h3);
            bf16 l0 = __float2bfloat16(o0 - __bfloat162float(h0));
            bf16 l1 = __float2bfloat16(o1 - __bfloat162float(h1));
            bf16 l2 = __float2bfloat16(o2 - __bfloat162float(h2));
            bf16 l3 = __float2bfloat16(o3 - __bfloat162float(h3));
            *(bf162*)(clo + g0) = bf162(l0, l1);
            *(bf162*)(clo + g1) = bf162(l2, l3);
        }
    }
}

// ---------------------------------------------------------------------------
extern "C" void kernel_launch(void* const* d_in, const int* in_sizes, int n_in,
                              void* d_out, int out_size)
{
    const float* x  = (const float*)d_in[0];
    const unsigned char* mask = (const unsigned char*)d_in[1];
    const float* Wq = (const float*)d_in[2];
    const float* bq = (const float*)d_in[3];
    const float* Wk = (const float*)d_in[4];
    const float* bk = (const float*)d_in[5];
    const float* Wv = (const float*)d_in[6];
    const float* bv = (const float*)d_in[7];
    const float* Wo = (const float*)d_in[8];
    const float* bo = (const float*)d_in[9];
    float* out = (float*)d_out;

    bf16 *xhi, *xlo, *qhi, *qlo, *khi, *klo, *vhi, *vlo, *whi, *wlo;
    cudaGetSymbolAddress((void**)&xhi, g_xhi);
    cudaGetSymbolAddress((void**)&xlo, g_xlo);
    cudaGetSymbolAddress((void**)&qhi, g_qhi);
    cudaGetSymbolAddress((void**)&qlo, g_qlo);
    cudaGetSymbolAddress((void**)&khi, g_khi);
    cudaGetSymbolAddress((void**)&klo, g_klo);
    cudaGetSymbolAddress((void**)&vhi, g_vhi);
    cudaGetSymbolAddress((void**)&vlo, g_vlo);
    cudaGetSymbolAddress((void**)&whi, g_whi);
    cudaGetSymbolAddress((void**)&wlo, g_wlo);

    const long long out_elems = (long long)NTOK * EMBED;
    const long long probs_elems = (long long)HEADS * CDIM * RDIM * RDIM;
    int write_probs = ((long long)out_size >= out_elems + probs_elems) ? 1 : 0;
    float* probs = write_probs ? (out + out_elems) : nullptr;

    const int gemm_smem = 2 * STAGEB;   // 81920
    cudaFuncSetAttribute(mma_gemm_qkv, cudaFuncAttributeMaxDynamicSharedMemorySize, gemm_smem);
    cudaFuncSetAttribute(mma_gemm_out, cudaFuncAttributeMaxDynamicSharedMemorySize, gemm_smem);
    cudaFuncSetAttribute(attn_mma, cudaFuncAttributeMaxDynamicSharedMemorySize, AT_SMEM);

    const size_t WSZ = (size_t)EMBED * EMBED;
    const int xn4 = (int)(((size_t)NTOK * EMBED) / 4);
    const int wn4 = (int)(WSZ / 4);

    split_kernel<<<(xn4 + 255) / 256, 256>>>((const float4*)x, xhi, xlo, xn4);
    {
        dim3 wgrid((wn4 + 255) / 256, 4);
        split_w_kernel<<<wgrid, 256>>>((const float4*)Wq, (const float4*)Wk,
                                       (const float4*)Wv, (const float4*)Wo,
                                       whi, wlo, wn4);
    }

    dim3 qkvgrid(NTOK / 128, 18);
    mma_gemm_qkv<<<qkvgrid, 256, gemm_smem>>>(xhi, xlo, whi, wlo,
                                              bq, bk, bv,
                                              qhi, qlo, khi, klo, vhi, vlo);

    dim3 agrid(CDIM, HEADS);
    attn_mma<<<agrid, 256, AT_SMEM>>>(qhi, qlo, khi, klo, vhi, vlo,
                                      mask, probs, xhi, xlo, write_probs);

    dim3 ogrid(NTOK / 128, EMBED / 128);
    mma_gemm_out<<<ogrid, 256, gemm_smem>>>(xhi, xlo, whi + 3 * WSZ, wlo + 3 * WSZ,
                                            bo, out);
}